// round 13
// baseline (speedup 1.0000x reference)
#include <cuda_runtime.h>
#include <cstdint>

#define BB    4
#define CINC  128
#define COUTC 64
#define HUPC  128
#define RESOC 256
#define NPTSC 100000

typedef unsigned long long ull;
typedef unsigned short u16;
typedef unsigned int u32;

// ---------------- scratch (static device globals; no allocs allowed) -------
__device__ __align__(16) u16 g_in_h[(size_t)BB*RESOC*RESOC*CINC];   // 64 MB bf16 hi
__device__ __align__(16) u16 g_in_l[(size_t)BB*RESOC*RESOC*CINC];   // 64 MB bf16 lo
__device__ __align__(16) u16 g_x1h [(size_t)BB*RESOC*RESOC*COUTC];  // 32 MB
__device__ __align__(16) u16 g_x1l [(size_t)BB*RESOC*RESOC*COUTC];  // 32 MB
__device__ float g_xt [(size_t)BB*RESOC*RESOC*COUTC];               // 64 MB f32 ch-last x
__device__ unsigned g_cnt [BB*RESOC*RESOC];
// pre-swizzled conv weight tiles: [tap][cb][64oc x 64ch]
__device__ __align__(16) u16 g_w1h[9*2*4096];
__device__ __align__(16) u16 g_w1l[9*2*4096];
__device__ __align__(16) u16 g_w2h[9*1*4096];
__device__ __align__(16) u16 g_w2l[9*1*4096];
// pre-swizzled point-MLP weights
__device__ __align__(16) u16 g_pw1h[8192];    // Wf1 [128j][64k]
__device__ __align__(16) u16 g_pw1l[8192];
__device__ __align__(16) u16 g_pw2h[4*4096];  // [kc][64o][64k]: kc0,1=Wf2, kc2,3=Wfc
__device__ __align__(16) u16 g_pw2l[4*4096];
// pre-swizzled upconv weights: [cb][256 n][64 ch], n = o*4+d*2+k
__device__ __align__(16) u16 g_wuh[2*16384];
__device__ __align__(16) u16 g_wul[2*16384];
__device__ __align__(16) u16 g_wch[2*16384];
__device__ __align__(16) u16 g_wcl[2*16384];

// ---------------- mma helpers ---------------------------------------------
__device__ __forceinline__ uint32_t smem_u32(const void* p) {
    uint32_t a;
    asm("{ .reg .u64 t; cvta.to.shared.u64 t, %1; cvt.u32.u64 %0, t; }" : "=r"(a) : "l"(p));
    return a;
}
#define SWZ128(off) ((off) ^ (((off) >> 3) & 0x70))

__device__ __forceinline__ void ldsm_x4(uint32_t addr, uint32_t* r) {
    asm volatile("ldmatrix.sync.aligned.m8n8.x4.shared.b16 {%0,%1,%2,%3}, [%4];"
        : "=r"(r[0]), "=r"(r[1]), "=r"(r[2]), "=r"(r[3]) : "r"(addr));
}
__device__ __forceinline__ void mma_bf16(float* d, const uint32_t* a, const uint32_t* b) {
    asm volatile("mma.sync.aligned.m16n8k16.row.col.f32.bf16.bf16.f32 "
        "{%0,%1,%2,%3}, {%4,%5,%6,%7}, {%8,%9}, {%0,%1,%2,%3};"
        : "+f"(d[0]), "+f"(d[1]), "+f"(d[2]), "+f"(d[3])
        : "r"(a[0]), "r"(a[1]), "r"(a[2]), "r"(a[3]), "r"(b[0]), "r"(b[1]));
}

// bf16 split helpers
__device__ __forceinline__ unsigned bfpair(float lo_e, float hi_e) {
    unsigned r; asm("cvt.rn.bf16x2.f32 %0, %1, %2;" : "=r"(r) : "f"(hi_e), "f"(lo_e)); return r;
}
__device__ __forceinline__ float bflo_f(unsigned w) { return __uint_as_float(w << 16); }
__device__ __forceinline__ float bfhi_f(unsigned w) { return __uint_as_float(w & 0xffff0000u); }

__device__ __forceinline__ void cvt_hilo8(const float* f, uint4& hv, uint4& lv) {
    unsigned h0 = bfpair(f[0], f[1]);
    unsigned h1 = bfpair(f[2], f[3]);
    unsigned h2 = bfpair(f[4], f[5]);
    unsigned h3 = bfpair(f[6], f[7]);
    hv = make_uint4(h0, h1, h2, h3);
    float l0 = f[0] - bflo_f(h0), l1 = f[1] - bfhi_f(h0);
    float l2 = f[2] - bflo_f(h1), l3 = f[3] - bfhi_f(h1);
    float l4 = f[4] - bflo_f(h2), l5 = f[5] - bfhi_f(h2);
    float l6 = f[6] - bflo_f(h3), l7 = f[7] - bfhi_f(h3);
    lv = make_uint4(bfpair(l0, l1), bfpair(l2, l3), bfpair(l4, l5), bfpair(l6, l7));
}

// ---------------- zero fea + counts ---------------------------------------
__global__ __launch_bounds__(256) void zero_kernel(float* __restrict__ fea) {
    size_t i = (size_t)blockIdx.x * 256 + threadIdx.x;
    size_t stride = (size_t)gridDim.x * 256;
    float4 z4 = make_float4(0.f, 0.f, 0.f, 0.f);
    for (size_t e = i; e < (size_t)BB*COUTC*RESOC*RESOC/4; e += stride)
        ((float4*)fea)[e] = z4;
    for (size_t e = i; e < BB*RESOC*RESOC/4; e += stride)
        ((uint4*)g_cnt)[e] = make_uint4(0u,0u,0u,0u);
}

// ---------------- weight pre-convert: f32 -> bf16 hi/lo, pre-swizzled -----
__global__ __launch_bounds__(256) void wconv_kernel(
    const float* __restrict__ W1, const float* __restrict__ W2,
    const float* __restrict__ Wf1, const float* __restrict__ Wf2,
    const float* __restrict__ Wfc, const float* __restrict__ W_up,
    const float* __restrict__ Wc)
{
    int t = blockIdx.x * 256 + threadIdx.x;
    if (t < 73728) {
        int tap = t % 9, c = (t / 9) % 128, o = t / 1152;
        float f = W1[t];
        u16 hi = (u16)(bfpair(f, 0.f) & 0xffff);
        float lf = f - bflo_f(hi);
        u16 lo = (u16)(bfpair(lf, 0.f) & 0xffff);
        unsigned idx = (tap*2 + (c >> 6))*4096 + (SWZ128((unsigned)(o*128 + (c & 63)*2)) >> 1);
        g_w1h[idx] = hi; g_w1l[idx] = lo;
    } else if (t < 110592) {
        int t2 = t - 73728;
        int tap = t2 % 9, c = (t2 / 9) % 64, o = t2 / 576;
        float f = W2[t2];
        u16 hi = (u16)(bfpair(f, 0.f) & 0xffff);
        float lf = f - bflo_f(hi);
        u16 lo = (u16)(bfpair(lf, 0.f) & 0xffff);
        unsigned idx = tap*4096 + (SWZ128((unsigned)(o*128 + c*2)) >> 1);
        g_w2h[idx] = hi; g_w2l[idx] = lo;
    } else if (t < 118784) {
        int e = t - 110592;
        int j = e >> 6, k = e & 63;
        float f = Wf1[j*64 + k];
        u16 hi = (u16)(bfpair(f, 0.f) & 0xffff);
        float lf = f - bflo_f(hi);
        u16 lo = (u16)(bfpair(lf, 0.f) & 0xffff);
        unsigned idx = SWZ128((unsigned)(j*128 + k*2)) >> 1;
        g_pw1h[idx] = hi; g_pw1l[idx] = lo;
    } else if (t < 135168) {
        int e = t - 118784;
        int which = e >> 13;           // 0: Wf2, 1: Wfc
        int e2 = e & 8191;
        int o = e2 >> 7, k = e2 & 127;
        float f = which ? Wfc[o*128 + k] : Wf2[o*128 + k];
        u16 hi = (u16)(bfpair(f, 0.f) & 0xffff);
        float lf = f - bflo_f(hi);
        u16 lo = (u16)(bfpair(lf, 0.f) & 0xffff);
        unsigned idx = (which*2 + (k >> 6))*4096 + (SWZ128((unsigned)(o*128 + (k & 63)*2)) >> 1);
        g_pw2h[idx] = hi; g_pw2l[idx] = lo;
    } else if (t < 135168 + 65536) {
        int e = t - 135168;
        int which = e >> 15;           // 0: W_up, 1: Wc
        int e2 = e & 32767;            // c*256 + n
        int c = e2 >> 8, n = e2 & 255;
        float f = which ? Wc[e2] : W_up[e2];
        u16 hi = (u16)(bfpair(f, 0.f) & 0xffff);
        float lf = f - bflo_f(hi);
        u16 lo = (u16)(bfpair(lf, 0.f) & 0xffff);
        unsigned idx = (c >> 6)*16384 + (SWZ128((unsigned)(n*128 + (c & 63)*2)) >> 1);
        if (which) { g_wch[idx] = hi; g_wcl[idx] = lo; }
        else       { g_wuh[idx] = hi; g_wul[idx] = lo; }
    }
}

// ---------------- HMMA 2x2 up-conv (split-bf16) ---------------------------
#define UPC_SMEM (98304 + 8704)
template<int DST>
__global__ __launch_bounds__(256, 2) void upconv_mma_kernel(
    const float* __restrict__ src, const float* __restrict__ bias,
    float* __restrict__ xout)
{
    extern __shared__ char smem[];
    const uint32_t sb = smem_u32(smem);
    float* in_s = (float*)(smem + 98304);

    const int t = threadIdx.x;
    const int lane = t & 31, w = t >> 5;
    const int px0 = (w & 1) * 32;
    const int n0  = (w >> 1) * 64;
    const int w0 = blockIdx.x * 64, h = blockIdx.y, b = blockIdx.z;

    const u16* __restrict__ wth = DST ? g_wch : g_wuh;
    const u16* __restrict__ wtl = DST ? g_wcl : g_wul;

#pragma unroll 1
    for (int half = 0; half < 4; half++) {
        int cb = half >> 1, sub = half & 1;
        int c0 = cb*64 + sub*32;
        {
            int c = t >> 3, pg = t & 7;
            const float* sp = &src[(((size_t)(b*CINC + c0 + c)*HUPC) + h)*HUPC + w0 + pg*8];
            float4 u0 = ((const float4*)sp)[0];
            float4 u1 = ((const float4*)sp)[1];
            float* dd = &in_s[c*68 + pg*8];
            dd[0]=u0.x; dd[1]=u0.y; dd[2]=u0.z; dd[3]=u0.w;
            dd[4]=u1.x; dd[5]=u1.y; dd[6]=u1.z; dd[7]=u1.w;
        }
        __syncthreads();
        {
            int px = t & 63, oct = t >> 6;
            float f[8];
#pragma unroll
            for (int i = 0; i < 8; i++) f[i] = in_s[(oct*8 + i)*68 + px];
            uint4 hv, lv; cvt_hilo8(f, hv, lv);
            unsigned sw = SWZ128((unsigned)(px*128 + (sub*32 + oct*8)*2));
            *(uint4*)(smem + cb*8192 + sw)         = hv;
            *(uint4*)(smem + 16384 + cb*8192 + sw) = lv;
        }
        __syncthreads();
    }

    float d[2][8][4];
#pragma unroll
    for (int mi = 0; mi < 2; mi++)
#pragma unroll
        for (int ni = 0; ni < 8; ni++)
#pragma unroll
            for (int r = 0; r < 4; r++) d[mi][ni][r] = 0.f;

#pragma unroll 1
    for (int cb = 0; cb < 2; cb++) {
        {
            const uint4* bhp = (const uint4*)(wth + cb*16384);
            const uint4* blp = (const uint4*)(wtl + cb*16384);
            uint4* dh = (uint4*)(smem + 32768);
            uint4* dl = (uint4*)(smem + 65536);
#pragma unroll
            for (int i = 0; i < 8; i++) { dh[t + i*256] = bhp[t + i*256]; dl[t + i*256] = blp[t + i*256]; }
        }
        __syncthreads();
        const uint32_t sah = sb + cb*8192;
        const uint32_t sal = sb + 16384 + cb*8192;
#pragma unroll
        for (int ks = 0; ks < 4; ks++) {
            uint32_t ah[2][4], al[2][4], bh[4][4], bl[4][4];
            const int arow  = lane & 15;
            const int acolb = ks*32 + (lane >> 4)*16;
            ldsm_x4(sah + SWZ128((px0 +      arow)*128 + acolb), ah[0]);
            ldsm_x4(sah + SWZ128((px0 + 16 + arow)*128 + acolb), ah[1]);
            ldsm_x4(sal + SWZ128((px0 +      arow)*128 + acolb), al[0]);
            ldsm_x4(sal + SWZ128((px0 + 16 + arow)*128 + acolb), al[1]);
            const int brow  = (lane & 7) + ((lane >> 4)*8);
            const int bcolb = ks*32 + ((lane >> 3) & 1)*16;
#pragma unroll
            for (int g = 0; g < 4; g++) {
                ldsm_x4(sb + 32768 + SWZ128((n0 + g*16 + brow)*128 + bcolb), bh[g]);
                ldsm_x4(sb + 65536 + SWZ128((n0 + g*16 + brow)*128 + bcolb), bl[g]);
            }
            // term-major issue: per-accumulator order stays hh -> hl -> lh
#pragma unroll
            for (int term = 0; term < 3; term++)
#pragma unroll
                for (int mi = 0; mi < 2; mi++)
#pragma unroll
                    for (int g = 0; g < 4; g++) {
                        const uint32_t* A = (term == 2) ? al[mi] : ah[mi];
                        const uint32_t* B = (term == 1) ? bl[g]  : bh[g];
                        mma_bf16(d[mi][g*2],     A, &B[0]);
                        mma_bf16(d[mi][g*2 + 1], A, &B[2]);
                    }
        }
        __syncthreads();
    }

    float* ep = (float*)smem;
    const int rr  = lane >> 2;
    const int rc2 = (lane & 3) * 2;
#pragma unroll
    for (int mi = 0; mi < 2; mi++)
#pragma unroll
    for (int ni = 0; ni < 8; ni++) {
        int n = n0 + (ni >> 1)*16 + (ni & 1)*8 + rc2;
#pragma unroll
        for (int hh = 0; hh < 2; hh++) {
            int px = px0 + mi*16 + rr + hh*8;
            *(float2*)&ep[px*260 + n] = make_float2(d[mi][ni][hh*2], d[mi][ni][hh*2 + 1]);
        }
    }
    __syncthreads();

    if (DST == 0) {
        int px = t >> 2, dk = t & 3;
        int dd = dk >> 1, k = dk & 1;
        size_t base = (((size_t)(b*RESOC + 2*h + dd)*RESOC) + 2*(w0 + px) + k)*CINC;
#pragma unroll
        for (int oct = 0; oct < 8; oct++) {
            float f[8];
#pragma unroll
            for (int i = 0; i < 8; i++)
                f[i] = ep[px*260 + (oct*8 + i)*4 + dk] + bias[oct*8 + i];
            uint4 hv, lv; cvt_hilo8(f, hv, lv);
            *(uint4*)&g_in_h[base + oct*8] = hv;
            *(uint4*)&g_in_l[base + oct*8] = lv;
        }
    } else {
        int o = t >> 2, dd = (t >> 1) & 1, half = t & 1;
        float bv = bias[o];
        size_t base = (((size_t)(b*COUTC + o)*RESOC) + 2*h + dd)*RESOC + 2*w0 + half*64;
#pragma unroll
        for (int g = 0; g < 16; g++) {
            int p0 = half*32 + g*2;
            float v0 = ep[ p0     *260 + o*4 + dd*2 + 0] + bv;
            float v1 = ep[ p0     *260 + o*4 + dd*2 + 1] + bv;
            float v2 = ep[(p0 + 1)*260 + o*4 + dd*2 + 0] + bv;
            float v3 = ep[(p0 + 1)*260 + o*4 + dd*2 + 1] + bv;
            *(float4*)&xout[base + g*4] = make_float4(v0, v1, v2, v3);
        }
    }
}

// ---------------- transpose from_down cm -> g_in_h/l ch 64..127 -----------
__global__ __launch_bounds__(256) void transpose_kernel(const float* __restrict__ fd) {
    __shared__ float s[64][33];
    int t = threadIdx.x;
    int xb = blockIdx.x, y = blockIdx.y, b = blockIdx.z;
#pragma unroll
    for (int i = 0; i < 8; i++) {
        int e = t + i*256;
        int c = e >> 5, px = e & 31;
        s[c][px] = fd[(((size_t)(b*64 + c)*RESOC) + y)*RESOC + xb*32 + px];
    }
    __syncthreads();
    int px = t >> 3, q = t & 7;
    float f[8];
#pragma unroll
    for (int i = 0; i < 8; i++) f[i] = s[q*8 + i][px];
    uint4 hv, lv; cvt_hilo8(f, hv, lv);
    size_t base = (((size_t)(b*RESOC + y)*RESOC) + xb*32 + px)*CINC + 64 + q*8;
    *(uint4*)&g_in_h[base] = hv;
    *(uint4*)&g_in_l[base] = lv;
}

// ---------------- HMMA 3x3 conv, A-strip resident (split-bf16) ------------
#define CV_AH(s) ((s)*16896)
#define CV_AL(s) (50688 + (s)*16896)
#define CV_B(q)  (101376 + (q)*16384)
#define CV_SMEM  134144

template<int MODE>
__global__ __launch_bounds__(256) void conv_mma_kernel(
    const float* __restrict__ bias, float* __restrict__ xout)
{
    constexpr int CIN = (MODE == 1) ? 128 : 64;
    extern __shared__ char smem[];
    const uint32_t sb = smem_u32(smem);

    const int t = threadIdx.x;
    const int lane = t & 31, w = t >> 5;
    const int px0 = (w & 3) * 32, oc0 = (w >> 2) * 32;
    const int x0 = blockIdx.x * 128, y = blockIdx.y, b = blockIdx.z;

    const u16* __restrict__ srch = (MODE == 1) ? g_in_h : g_x1h;
    const u16* __restrict__ srcl = (MODE == 1) ? g_in_l : g_x1l;
    const u16* __restrict__ wth  = (MODE == 1) ? g_w1h : g_w2h;
    const u16* __restrict__ wtl  = (MODE == 1) ? g_w1l : g_w2l;

    float d[2][4][4];
#pragma unroll
    for (int mi = 0; mi < 2; mi++)
#pragma unroll
        for (int ni = 0; ni < 4; ni++)
#pragma unroll
            for (int r = 0; r < 4; r++) d[mi][ni][r] = 0.f;

#pragma unroll 1
    for (int cb = 0; cb < CIN/64; cb++) {
        {
            const uint4 z = make_uint4(0,0,0,0);
#pragma unroll 1
            for (int e = t; e < 3*130*8; e += 256) {
                int ri = e >> 3, i = e & 7;
                int s = ri / 130, row = ri % 130;
                int gy = y + s - 1, gx = x0 + row - 1;
                bool ok = (gy >= 0 && gy < 256 && gx >= 0 && gx < 256);
                uint4 hv = z, lv = z;
                if (ok) {
                    size_t off = (((size_t)(b*RESOC + gy)*RESOC) + gx)*CIN + cb*64 + i*8;
                    hv = *(const uint4*)(srch + off);
                    lv = *(const uint4*)(srcl + off);
                }
                unsigned sw = SWZ128((unsigned)(row*128 + i*16));
                *(uint4*)(smem + CV_AH(s) + sw) = hv;
                *(uint4*)(smem + CV_AL(s) + sw) = lv;
            }
        }
#pragma unroll 1
        for (int tap = 0; tap < 9; tap++) {
            const int s = tap / 3, dx = tap % 3 - 1;
            const int gy = y + s - 1;
            if (gy < 0 || gy > 255) continue;
            const int q = tap & 1;
            {
                const uint4* bh = (const uint4*)(wth + (tap*(CIN/64) + cb)*4096);
                const uint4* bl = (const uint4*)(wtl + (tap*(CIN/64) + cb)*4096);
                *(uint4*)(smem + CV_B(q) + t*32)             = bh[t*2];
                *(uint4*)(smem + CV_B(q) + t*32 + 16)        = bh[t*2 + 1];
                *(uint4*)(smem + CV_B(q) + 8192 + t*32)      = bl[t*2];
                *(uint4*)(smem + CV_B(q) + 8192 + t*32 + 16) = bl[t*2 + 1];
            }
            __syncthreads();
            const uint32_t sah = sb + CV_AH(s);
            const uint32_t sal = sb + CV_AL(s);
            const uint32_t sbh = sb + CV_B(q);
            const uint32_t sbl = sbh + 8192;
            const int ar = px0 + (lane & 15) + 1 + dx;
#pragma unroll
            for (int ks = 0; ks < 4; ks++) {
                uint32_t ah[2][4], al[2][4], bh[2][4], bl[2][4];
                const int acolb = ks*32 + (lane >> 4)*16;
                ldsm_x4(sah + SWZ128( ar      *128 + acolb), ah[0]);
                ldsm_x4(sah + SWZ128((ar + 16)*128 + acolb), ah[1]);
                ldsm_x4(sal + SWZ128( ar      *128 + acolb), al[0]);
                ldsm_x4(sal + SWZ128((ar + 16)*128 + acolb), al[1]);
                const int brow  = (lane & 7) + ((lane >> 4)*8);
                const int bcolb = ks*32 + ((lane >> 3) & 1)*16;
                ldsm_x4(sbh + SWZ128((oc0 +      brow)*128 + bcolb), bh[0]);
                ldsm_x4(sbh + SWZ128((oc0 + 16 + brow)*128 + bcolb), bh[1]);
                ldsm_x4(sbl + SWZ128((oc0 +      brow)*128 + bcolb), bl[0]);
                ldsm_x4(sbl + SWZ128((oc0 + 16 + brow)*128 + bcolb), bl[1]);
                // term-major issue: per-accumulator order stays hh -> hl -> lh
#pragma unroll
                for (int term = 0; term < 3; term++)
#pragma unroll
                    for (int mi = 0; mi < 2; mi++)
#pragma unroll
                        for (int g = 0; g < 2; g++) {
                            const uint32_t* A = (term == 2) ? al[mi] : ah[mi];
                            const uint32_t* B = (term == 1) ? bl[g]  : bh[g];
                            mma_bf16(d[mi][g*2],     A, &B[0]);
                            mma_bf16(d[mi][g*2 + 1], A, &B[2]);
                        }
            }
        }
        __syncthreads();
    }

    const int rr  = lane >> 2;
    const int rc2 = (lane & 3) * 2;
#pragma unroll
    for (int mi = 0; mi < 2; mi++)
#pragma unroll
    for (int ni = 0; ni < 4; ni++) {
        int oc = oc0 + (ni >> 1)*16 + (ni & 1)*8 + rc2;
        float b0v = bias[oc], b1v = bias[oc + 1];
#pragma unroll
        for (int hh = 0; hh < 2; hh++) {
            int pxl = px0 + mi*16 + rr + hh*8;
            int x = x0 + pxl;
            float v0 = fmaxf(d[mi][ni][hh*2 + 0] + b0v, 0.f);
            float v1 = fmaxf(d[mi][ni][hh*2 + 1] + b1v, 0.f);
            if (MODE == 1) {
                size_t base = (((size_t)(b*RESOC + y)*RESOC) + x)*COUTC + oc;
                unsigned hi = bfpair(v0, v1);
                float l0 = v0 - bflo_f(hi), l1 = v1 - bfhi_f(hi);
                unsigned lo = bfpair(l0, l1);
                *(u32*)&g_x1h[base] = hi;
                *(u32*)&g_x1l[base] = lo;
            } else {
                size_t cm0 = (((size_t)(b*COUTC + oc)*RESOC) + y)*RESOC + x;
                size_t cm1 = cm0 + (size_t)RESOC*RESOC;
                float r0 = v0 + xout[cm0], r1 = v1 + xout[cm1];
                xout[cm0] = r0; xout[cm1] = r1;
                *(float2*)&g_xt[(((size_t)(b*RESOC + y)*RESOC) + x)*COUTC + oc] =
                    make_float2(r0, r1);
            }
        }
    }
}

// ---------------- fused point pipeline (persistent, HMMA split-bf16) ------
#define PT_A1H 0
#define PT_A1L 8192
#define PT_W1H 16384
#define PT_W1L 32768
#define PT_HH  49152
#define PT_HL  81920
#define PT_W2H 114688
#define PT_W2L 147456
#define PT_IDX 180224
#define PT_SMEM (180224 + 512)
#define PT_TILES 6250

__global__ __launch_bounds__(256) void points_kernel(
    const float* __restrict__ p,   const float* __restrict__ c_last,
    const float* __restrict__ bf1, const float* __restrict__ bf2,
    const float* __restrict__ bfc,
    float* __restrict__ fea, float* __restrict__ cout)
{
    extern __shared__ char smem[];
    const uint32_t sb = smem_u32(smem);
    int* idx_s = (int*)(smem + PT_IDX);

    const int t = threadIdx.x;
    const int lane = t & 31, wid = t >> 5;

    {
        const uint4* s;
        uint4* dd;
        s = (const uint4*)g_pw1h; dd = (uint4*)(smem + PT_W1H);
        for (int i = t; i < 1024; i += 256) dd[i] = s[i];
        s = (const uint4*)g_pw1l; dd = (uint4*)(smem + PT_W1L);
        for (int i = t; i < 1024; i += 256) dd[i] = s[i];
        s = (const uint4*)g_pw2h; dd = (uint4*)(smem + PT_W2H);
        for (int i = t; i < 2048; i += 256) dd[i] = s[i];
        s = (const uint4*)g_pw2l; dd = (uint4*)(smem + PT_W2L);
        for (int i = t; i < 2048; i += 256) dd[i] = s[i];
    }

    const int rr  = lane >> 2;
    const int rc2 = (lane & 3) * 2;

#pragma unroll 1
    for (int tile = blockIdx.x; tile < PT_TILES; tile += gridDim.x) {
        {
            int pt = t >> 2, part = t & 3;
            int g = tile*64 + pt;
            int b = g / NPTSC;
            float px = p[(size_t)g*3 + 0], py = p[(size_t)g*3 + 1];
            float ix = fminf(fmaxf(px*255.f, 0.f), 255.f);
            float iy = fminf(fmaxf(py*255.f, 0.f), 255.f);
            float x0f = floorf(ix), y0f = floorf(iy);
            int x0 = (int)x0f, y0i = (int)y0f;
            int x1 = min(x0 + 1, 255), y1 = min(y0i + 1, 255);
            float wx = ix - x0f, wy = iy - y0f;
            float w00 = (1.f-wx)*(1.f-wy), w01 = wx*(1.f-wy);
            float w10 = (1.f-wx)*wy,       w11 = wx*wy;
            const float* f00 = &g_xt[(((size_t)(b*RESOC + y0i)*RESOC) + x0)*COUTC + part*16];
            const float* f01 = &g_xt[(((size_t)(b*RESOC + y0i)*RESOC) + x1)*COUTC + part*16];
            const float* f10 = &g_xt[(((size_t)(b*RESOC + y1 )*RESOC) + x0)*COUTC + part*16];
            const float* f11 = &g_xt[(((size_t)(b*RESOC + y1 )*RESOC) + x1)*COUTC + part*16];
#pragma unroll
            for (int i = 0; i < 4; i++) {
                float4 a = *(const float4*)&f00[i*4];
                float4 bq = *(const float4*)&f01[i*4];
                float4 cq = *(const float4*)&f10[i*4];
                float4 dq = *(const float4*)&f11[i*4];
                float r0 = a.x*w00 + bq.x*w01 + cq.x*w10 + dq.x*w11;
                float r1 = a.y*w00 + bq.y*w01 + cq.y*w10 + dq.y*w11;
                float r2 = a.z*w00 + bq.z*w01 + cq.z*w10 + dq.z*w11;
                float r3 = a.w*w00 + bq.w*w01 + cq.w*w10 + dq.w*w11;
                unsigned h0 = bfpair(r0, r1), h1 = bfpair(r2, r3);
                float l0 = r0 - bflo_f(h0), l1 = r1 - bfhi_f(h0);
                float l2 = r2 - bflo_f(h1), l3 = r3 - bfhi_f(h1);
                unsigned q0 = bfpair(l0, l1), q1 = bfpair(l2, l3);
                unsigned sw = SWZ128((unsigned)(pt*128 + part*32 + (i >> 1)*16)) + (i & 1)*8;
                *(uint2*)(smem + PT_A1H + sw) = make_uint2(h0, h1);
                *(uint2*)(smem + PT_A1L + sw) = make_uint2(q0, q1);
            }
            if (part == 0) {
                int gx = min(max((int)(px*256.f), 0), 255);
                int gy = min(max((int)(py*256.f), 0), 255);
                int cell = gy*256 + gx;
                idx_s[pt] = cell;
                atomicAdd(&g_cnt[b*65536 + cell], 1u);
            }
            const float* cls = c_last + (size_t)g*128 + part*32;
            int kc = 2 + (part >> 1);
#pragma unroll
            for (int grp = 0; grp < 4; grp++) {
                float f[8];
                float4 u0 = ((const float4*)cls)[grp*2];
                float4 u1 = ((const float4*)cls)[grp*2 + 1];
                f[0]=u0.x; f[1]=u0.y; f[2]=u0.z; f[3]=u0.w;
                f[4]=u1.x; f[5]=u1.y; f[6]=u1.z; f[7]=u1.w;
                uint4 hv, lv; cvt_hilo8(f, hv, lv);
                int col = (part*32 + grp*8) & 63;
                unsigned sw = SWZ128((unsigned)(pt*128 + col*2));
                *(uint4*)(smem + PT_HH + kc*8192 + sw) = hv;
                *(uint4*)(smem + PT_HL + kc*8192 + sw) = lv;
            }
        }
        __syncthreads();

        {
            const int pt0 = (wid & 1) * 32;
            const int j0  = (wid >> 1) * 32;
            float d[2][4][4];
#pragma unroll
            for (int mi = 0; mi < 2; mi++)
#pragma unroll
                for (int ni = 0; ni < 4; ni++)
#pragma unroll
                    for (int r = 0; r < 4; r++) d[mi][ni][r] = 0.f;

#pragma unroll
            for (int ks = 0; ks < 4; ks++) {
                uint32_t ah[2][4], al[2][4], bh[2][4], bl[2][4];
                const int arow  = lane & 15;
                const int acolb = ks*32 + (lane >> 4)*16;
                ldsm_x4(sb + PT_A1H + SWZ128((pt0 +      arow)*128 + acolb), ah[0]);
                ldsm_x4(sb + PT_A1H + SWZ128((pt0 + 16 + arow)*128 + acolb), ah[1]);
                ldsm_x4(sb + PT_A1L + SWZ128((pt0 +      arow)*128 + acolb), al[0]);
                ldsm_x4(sb + PT_A1L + SWZ128((pt0 + 16 + arow)*128 + acolb), al[1]);
                const int brow  = (lane & 7) + ((lane >> 4)*8);
                const int bcolb = ks*32 + ((lane >> 3) & 1)*16;
                ldsm_x4(sb + PT_W1H + SWZ128((j0 +      brow)*128 + bcolb), bh[0]);
                ldsm_x4(sb + PT_W1H + SWZ128((j0 + 16 + brow)*128 + bcolb), bh[1]);
                ldsm_x4(sb + PT_W1L + SWZ128((j0 +      brow)*128 + bcolb), bl[0]);
                ldsm_x4(sb + PT_W1L + SWZ128((j0 + 16 + brow)*128 + bcolb), bl[1]);
                // term-major issue
#pragma unroll
                for (int term = 0; term < 3; term++)
#pragma unroll
                    for (int mi = 0; mi < 2; mi++)
#pragma unroll
                        for (int g = 0; g < 2; g++) {
                            const uint32_t* A = (term == 2) ? al[mi] : ah[mi];
                            const uint32_t* B = (term == 1) ? bl[g]  : bh[g];
                            mma_bf16(d[mi][g*2],     A, &B[0]);
                            mma_bf16(d[mi][g*2 + 1], A, &B[2]);
                        }
            }
#pragma unroll
            for (int mi = 0; mi < 2; mi++)
#pragma unroll
            for (int ni = 0; ni < 4; ni++) {
                int j = j0 + (ni >> 1)*16 + (ni & 1)*8 + rc2;
                float b0v = bf1[j], b1v = bf1[j + 1];
                int kc = j >> 6, col = j & 63;
#pragma unroll
                for (int hh = 0; hh < 2; hh++) {
                    int pt = pt0 + mi*16 + rr + hh*8;
                    float v0 = fmaxf(d[mi][ni][hh*2 + 0] + b0v, 0.f);
                    float v1 = fmaxf(d[mi][ni][hh*2 + 1] + b1v, 0.f);
                    unsigned hi = bfpair(v0, v1);
                    float l0 = v0 - bflo_f(hi), l1 = v1 - bfhi_f(hi);
                    unsigned lo = bfpair(l0, l1);
                    unsigned sw = SWZ128((unsigned)(pt*128 + (col & ~7)*2)) + (col & 7)*2;
                    *(u32*)(smem + PT_HH + kc*8192 + sw) = hi;
                    *(u32*)(smem + PT_HL + kc*8192 + sw) = lo;
                }
            }
        }
        __syncthreads();

        {
            const int m0 = (wid & 3) * 16;
            const int o0 = (wid >> 2) * 32;
            float d[4][4];
#pragma unroll
            for (int ni = 0; ni < 4; ni++)
#pragma unroll
                for (int r = 0; r < 4; r++) d[ni][r] = 0.f;

#pragma unroll 1
            for (int ks = 0; ks < 16; ks++) {
                const int kc = ks >> 2, kk = ks & 3;
                uint32_t ah[4], al[4], bh[2][4], bl[2][4];
                const int arow  = lane & 15;
                const int acolb = kk*32 + (lane >> 4)*16;
                ldsm_x4(sb + PT_HH + kc*8192 + SWZ128((m0 + arow)*128 + acolb), ah);
                ldsm_x4(sb + PT_HL + kc*8192 + SWZ128((m0 + arow)*128 + acolb), al);
                const int brow  = (lane & 7) + ((lane >> 4)*8);
                const int bcolb = kk*32 + ((lane >> 3) & 1)*16;
                ldsm_x4(sb + PT_W2H + kc*8192 + SWZ128((o0 +      brow)*128 + bcolb), bh[0]);
                ldsm_x4(sb + PT_W2H + kc*8192 + SWZ128((o0 + 16 + brow)*128 + bcolb), bh[1]);
                ldsm_x4(sb + PT_W2L + kc*8192 + SWZ128((o0 +      brow)*128 + bcolb), bl[0]);
                ldsm_x4(sb + PT_W2L + kc*8192 + SWZ128((o0 + 16 + brow)*128 + bcolb), bl[1]);
                // term-major issue
#pragma unroll
                for (int term = 0; term < 3; term++)
#pragma unroll
                    for (int g = 0; g < 2; g++) {
                        const uint32_t* A = (term == 2) ? al : ah;
                        const uint32_t* B = (term == 1) ? bl[g] : bh[g];
                        mma_bf16(d[g*2],     A, &B[0]);
                        mma_bf16(d[g*2 + 1], A, &B[2]);
                    }
            }
#pragma unroll
            for (int ni = 0; ni < 4; ni++) {
                int o = o0 + (ni >> 1)*16 + (ni & 1)*8 + rc2;
                float b0v = bf2[o] + bfc[o], b1v = bf2[o + 1] + bfc[o + 1];
#pragma unroll
                for (int hh = 0; hh < 2; hh++) {
                    int pt = m0 + rr + hh*8;
                    int g = tile*64 + pt;
                    int b = g / NPTSC;
                    int cell = idx_s[pt];
                    float cv0 = d[ni][hh*2 + 0] + b0v;
                    float cv1 = d[ni][hh*2 + 1] + b1v;
                    *(float2*)&cout[(size_t)g*64 + o] = make_float2(cv0, cv1);
                    atomicAdd(&fea[((size_t)(b*COUTC + o    ))*65536 + cell], cv0);
                    atomicAdd(&fea[((size_t)(b*COUTC + o + 1))*65536 + cell], cv1);
                }
            }
        }
        __syncthreads();
    }
}

// ---------------- scatter-mean finalize -----------------------------------
__global__ __launch_bounds__(256) void finalize_kernel(float* __restrict__ fea) {
    size_t i = (size_t)blockIdx.x * 256 + threadIdx.x;
    size_t stride = (size_t)gridDim.x * 256;
    for (size_t e = i; e < (size_t)BB*COUTC*RESOC*RESOC; e += stride) {
        unsigned cell = (unsigned)(e & 65535u);
        unsigned b = (unsigned)(e >> 22);
        unsigned c = g_cnt[b*65536 + cell];
        fea[e] *= 1.f / (float)(c > 1u ? c : 1u);
    }
}

// ---------------- launch ---------------------------------------------------
extern "C" void kernel_launch(void* const* d_in, const int* in_sizes, int n_in,
                              void* d_out, int out_size) {
    (void)in_sizes; (void)n_in; (void)out_size;
    const float* p         = (const float*)d_in[0];
    const float* from_up   = (const float*)d_in[1];
    const float* from_down = (const float*)d_in[2];
    const float* x_after   = (const float*)d_in[3];
    const float* c_last    = (const float*)d_in[4];
    const float* W_up      = (const float*)d_in[5];
    const float* b_up      = (const float*)d_in[6];
    const float* W1        = (const float*)d_in[7];
    const float* b1        = (const float*)d_in[8];
    const float* W2        = (const float*)d_in[9];
    const float* b2        = (const float*)d_in[10];
    const float* Wc        = (const float*)d_in[11];
    const float* bc        = (const float*)d_in[12];
    const float* Wf1       = (const float*)d_in[13];
    const float* bf1       = (const float*)d_in[14];
    const float* Wf2       = (const float*)d_in[15];
    const float* bf2       = (const float*)d_in[16];
    const float* Wfc       = (const float*)d_in[17];
    const float* bfc       = (const float*)d_in[18];

    float* out  = (float*)d_out;
    float* fea  = out;                        // (B,64,256,256)
    float* xout = out + (size_t)16777216;     // (B,64,256,256)
    float* cout = out + (size_t)33554432;     // (B,NPTS,64)

    static cudaStream_t s1 = nullptr, s2 = nullptr, s3 = nullptr;
    static cudaEvent_t eStart = nullptr, eW = nullptr, eZero = nullptr,
                       eUpc1 = nullptr, eTr = nullptr;
    if (!s1) {
        cudaStreamCreateWithFlags(&s1, cudaStreamNonBlocking);
        cudaStreamCreateWithFlags(&s2, cudaStreamNonBlocking);
        cudaStreamCreateWithFlags(&s3, cudaStreamNonBlocking);
        cudaEventCreateWithFlags(&eStart, cudaEventDisableTiming);
        cudaEventCreateWithFlags(&eW,     cudaEventDisableTiming);
        cudaEventCreateWithFlags(&eZero,  cudaEventDisableTiming);
        cudaEventCreateWithFlags(&eUpc1,  cudaEventDisableTiming);
        cudaEventCreateWithFlags(&eTr,    cudaEventDisableTiming);
        cudaFuncSetAttribute(points_kernel, cudaFuncAttributeMaxDynamicSharedMemorySize, PT_SMEM);
        cudaFuncSetAttribute(upconv_mma_kernel<0>, cudaFuncAttributeMaxDynamicSharedMemorySize, UPC_SMEM);
        cudaFuncSetAttribute(upconv_mma_kernel<1>, cudaFuncAttributeMaxDynamicSharedMemorySize, UPC_SMEM);
        cudaFuncSetAttribute(conv_mma_kernel<1>, cudaFuncAttributeMaxDynamicSharedMemorySize, CV_SMEM);
        cudaFuncSetAttribute(conv_mma_kernel<2>, cudaFuncAttributeMaxDynamicSharedMemorySize, CV_SMEM);
    }

    // fork point on the (possibly capturing) origin stream
    cudaEventRecord(eStart, 0);

    // origin: weight convert, then upconv0 (conv1's critical path)
    wconv_kernel<<<784, 256>>>(W1, W2, Wf1, Wf2, Wfc, W_up, Wc);
    cudaEventRecord(eW, 0);
    upconv_mma_kernel<0><<<dim3(2, 128, 4), 256, UPC_SMEM>>>(from_up, b_up, nullptr);

    // s1: zero fea + counts (needed only by points)
    cudaStreamWaitEvent(s1, eStart, 0);
    zero_kernel<<<2048, 256, 0, s1>>>(fea);
    cudaEventRecord(eZero, s1);

    // s2: upconv1 -> xout residual (needed only by conv2 epilogue)
    cudaStreamWaitEvent(s2, eW, 0);
    upconv_mma_kernel<1><<<dim3(2, 128, 4), 256, UPC_SMEM, s2>>>(x_after, bc, xout);
    cudaEventRecord(eUpc1, s2);

    // s3: transpose from_down (needed by conv1)
    cudaStreamWaitEvent(s3, eStart, 0);
    transpose_kernel<<<dim3(8, 256, 4), 256, 0, s3>>>(from_down);
    cudaEventRecord(eTr, s3);

    // origin: conv1 after upconv0 (ordered) + transpose (event)
    cudaStreamWaitEvent(0, eTr, 0);
    conv_mma_kernel<1><<<dim3(2, 256, 4), 256, CV_SMEM>>>(b1, nullptr);

    // conv2 after conv1 (ordered) + upconv1 (event)
    cudaStreamWaitEvent(0, eUpc1, 0);
    conv_mma_kernel<2><<<dim3(2, 256, 4), 256, CV_SMEM>>>(b2, xout);

    // points after conv2 (ordered) + zero (event)
    cudaStreamWaitEvent(0, eZero, 0);
    points_kernel<<<152, 256, PT_SMEM>>>(p, c_last, bf1, bf2, bfc, fea, cout);
    finalize_kernel<<<8192, 256>>>(fea);
}

// round 14
// speedup vs baseline: 1.3583x; 1.3583x over previous
#include <cuda_runtime.h>
#include <cstdint>

#define BB    4
#define CINC  128
#define COUTC 64
#define HUPC  128
#define RESOC 256
#define NPTSC 100000

typedef unsigned long long ull;
typedef unsigned short u16;
typedef unsigned int u32;

// ---------------- scratch (static device globals; no allocs allowed) -------
__device__ __align__(16) u16 g_in_h[(size_t)BB*RESOC*RESOC*CINC];   // 64 MB bf16 hi
__device__ __align__(16) u16 g_in_l[(size_t)BB*RESOC*RESOC*CINC];   // 64 MB bf16 lo
__device__ __align__(16) u16 g_x1h [(size_t)BB*RESOC*RESOC*COUTC];  // 32 MB
__device__ __align__(16) u16 g_x1l [(size_t)BB*RESOC*RESOC*COUTC];  // 32 MB
__device__ float g_xt [(size_t)BB*RESOC*RESOC*COUTC];               // 64 MB f32 ch-last x
__device__ unsigned g_cnt [BB*RESOC*RESOC];
// fragment-major conv weights: uint4 per (tap,cb,oh,g,ks,lane)
__device__ __align__(16) u16 g_w1fh[73728];
__device__ __align__(16) u16 g_w1fl[73728];
__device__ __align__(16) u16 g_w2fh[36864];
__device__ __align__(16) u16 g_w2fl[36864];
// fragment-major point-MLP weights
__device__ __align__(16) u16 g_pw1fh[8192];   // Wf1: (oh4,g2,ks4,lane32)
__device__ __align__(16) u16 g_pw1fl[8192];
__device__ __align__(16) u16 g_pw2fh[16384];  // W2cat: (kc4,oh2,g2,kk4,lane32)
__device__ __align__(16) u16 g_pw2fl[16384];
// pre-swizzled upconv weights: [cb][256 n][64 ch], n = o*4+d*2+k
__device__ __align__(16) u16 g_wuh[2*16384];
__device__ __align__(16) u16 g_wul[2*16384];
__device__ __align__(16) u16 g_wch[2*16384];
__device__ __align__(16) u16 g_wcl[2*16384];

// ---------------- mma helpers ---------------------------------------------
__device__ __forceinline__ uint32_t smem_u32(const void* p) {
    uint32_t a;
    asm("{ .reg .u64 t; cvta.to.shared.u64 t, %1; cvt.u32.u64 %0, t; }" : "=r"(a) : "l"(p));
    return a;
}
#define SWZ128(off) ((off) ^ (((off) >> 3) & 0x70))

__device__ __forceinline__ void ldsm_x4(uint32_t addr, uint32_t* r) {
    asm volatile("ldmatrix.sync.aligned.m8n8.x4.shared.b16 {%0,%1,%2,%3}, [%4];"
        : "=r"(r[0]), "=r"(r[1]), "=r"(r[2]), "=r"(r[3]) : "r"(addr));
}
__device__ __forceinline__ void mma_bf16(float* d, const uint32_t* a, const uint32_t* b) {
    asm volatile("mma.sync.aligned.m16n8k16.row.col.f32.bf16.bf16.f32 "
        "{%0,%1,%2,%3}, {%4,%5,%6,%7}, {%8,%9}, {%0,%1,%2,%3};"
        : "+f"(d[0]), "+f"(d[1]), "+f"(d[2]), "+f"(d[3])
        : "r"(a[0]), "r"(a[1]), "r"(a[2]), "r"(a[3]), "r"(b[0]), "r"(b[1]));
}

// bf16 split helpers
__device__ __forceinline__ unsigned bfpair(float lo_e, float hi_e) {
    unsigned r; asm("cvt.rn.bf16x2.f32 %0, %1, %2;" : "=r"(r) : "f"(hi_e), "f"(lo_e)); return r;
}
__device__ __forceinline__ float bflo_f(unsigned w) { return __uint_as_float(w << 16); }
__device__ __forceinline__ float bfhi_f(unsigned w) { return __uint_as_float(w & 0xffff0000u); }

__device__ __forceinline__ void cvt_hilo8(const float* f, uint4& hv, uint4& lv) {
    unsigned h0 = bfpair(f[0], f[1]);
    unsigned h1 = bfpair(f[2], f[3]);
    unsigned h2 = bfpair(f[4], f[5]);
    unsigned h3 = bfpair(f[6], f[7]);
    hv = make_uint4(h0, h1, h2, h3);
    float l0 = f[0] - bflo_f(h0), l1 = f[1] - bfhi_f(h0);
    float l2 = f[2] - bflo_f(h1), l3 = f[3] - bfhi_f(h1);
    float l4 = f[4] - bflo_f(h2), l5 = f[5] - bfhi_f(h2);
    float l6 = f[6] - bflo_f(h3), l7 = f[7] - bfhi_f(h3);
    lv = make_uint4(bfpair(l0, l1), bfpair(l2, l3), bfpair(l4, l5), bfpair(l6, l7));
}

// fragment element index inside a (16n x 16k) uint4 fragment:
// lane = (n&7)*4 + ((k&7)>>1), jj = ((n>>3)<<1)|(k>>3), e = k&1   (n,k in [0,16))
__device__ __forceinline__ unsigned frag_elem(int n16, int k16) {
    int lane = (n16 & 7)*4 + ((k16 & 7) >> 1);
    int jj = ((n16 >> 3) << 1) | ((k16 >> 3) & 1);
    int e = k16 & 1;
    return (unsigned)(lane*8 + jj*2 + e);
}

// ---------------- zero fea + counts ---------------------------------------
__global__ __launch_bounds__(256) void zero_kernel(float* __restrict__ fea) {
    size_t i = (size_t)blockIdx.x * 256 + threadIdx.x;
    size_t stride = (size_t)gridDim.x * 256;
    float4 z4 = make_float4(0.f, 0.f, 0.f, 0.f);
    for (size_t e = i; e < (size_t)BB*COUTC*RESOC*RESOC/4; e += stride)
        ((float4*)fea)[e] = z4;
    for (size_t e = i; e < BB*RESOC*RESOC/4; e += stride)
        ((uint4*)g_cnt)[e] = make_uint4(0u,0u,0u,0u);
}

// ---------------- weight pre-convert --------------------------------------
__global__ __launch_bounds__(256) void wconv_kernel(
    const float* __restrict__ W1, const float* __restrict__ W2,
    const float* __restrict__ Wf1, const float* __restrict__ Wf2,
    const float* __restrict__ Wfc, const float* __restrict__ W_up,
    const float* __restrict__ Wc)
{
    int t = blockIdx.x * 256 + threadIdx.x;
    if (t < 73728) {
        // W1 linear: o*1152 + c*9 + tap  -> fragment-major
        int tap = t % 9, c = (t / 9) % 128, o = t / 1152;
        float f = W1[t];
        u16 hi = (u16)(bfpair(f, 0.f) & 0xffff);
        float lf = f - bflo_f(hi);
        u16 lo = (u16)(bfpair(lf, 0.f) & 0xffff);
        int cb = c >> 6, ch = c & 63;
        int oh = o >> 5, g = (o >> 4) & 1;
        int ks = ch >> 4;
        unsigned idx4 = (unsigned)((((tap*2 + cb)*2 + oh)*2 + g)*4 + ks)*32;
        unsigned off = idx4*8 + frag_elem(o & 15, ch & 15);
        g_w1fh[off] = hi; g_w1fl[off] = lo;
    } else if (t < 110592) {
        int t2 = t - 73728;
        int tap = t2 % 9, c = (t2 / 9) % 64, o = t2 / 576;
        float f = W2[t2];
        u16 hi = (u16)(bfpair(f, 0.f) & 0xffff);
        float lf = f - bflo_f(hi);
        u16 lo = (u16)(bfpair(lf, 0.f) & 0xffff);
        int oh = o >> 5, g = (o >> 4) & 1;
        int ks = c >> 4;
        unsigned idx4 = (unsigned)(((tap*2 + oh)*2 + g)*4 + ks)*32;
        unsigned off = idx4*8 + frag_elem(o & 15, c & 15);
        g_w2fh[off] = hi; g_w2fl[off] = lo;
    } else if (t < 118784) {
        int e = t - 110592;
        int j = e >> 6, k = e & 63;
        float f = Wf1[j*64 + k];
        u16 hi = (u16)(bfpair(f, 0.f) & 0xffff);
        float lf = f - bflo_f(hi);
        u16 lo = (u16)(bfpair(lf, 0.f) & 0xffff);
        int oh = j >> 5, g = (j >> 4) & 1;
        int ks = k >> 4;
        unsigned idx4 = (unsigned)((oh*2 + g)*4 + ks)*32;
        unsigned off = idx4*8 + frag_elem(j & 15, k & 15);
        g_pw1fh[off] = hi; g_pw1fl[off] = lo;
    } else if (t < 135168) {
        int e = t - 118784;
        int which = e >> 13;           // 0: Wf2, 1: Wfc
        int e2 = e & 8191;
        int o = e2 >> 7, k = e2 & 127;
        float f = which ? Wfc[o*128 + k] : Wf2[o*128 + k];
        u16 hi = (u16)(bfpair(f, 0.f) & 0xffff);
        float lf = f - bflo_f(hi);
        u16 lo = (u16)(bfpair(lf, 0.f) & 0xffff);
        int kc = which*2 + (k >> 6);
        int kl64 = k & 63;
        int oh = o >> 5, g = (o >> 4) & 1;
        int kk = kl64 >> 4;
        unsigned idx4 = (unsigned)(((kc*2 + oh)*2 + g)*4 + kk)*32;
        unsigned off = idx4*8 + frag_elem(o & 15, kl64 & 15);
        g_pw2fh[off] = hi; g_pw2fl[off] = lo;
    } else if (t < 135168 + 65536) {
        int e = t - 135168;
        int which = e >> 15;           // 0: W_up, 1: Wc
        int e2 = e & 32767;            // c*256 + n
        int c = e2 >> 8, n = e2 & 255;
        float f = which ? Wc[e2] : W_up[e2];
        u16 hi = (u16)(bfpair(f, 0.f) & 0xffff);
        float lf = f - bflo_f(hi);
        u16 lo = (u16)(bfpair(lf, 0.f) & 0xffff);
        unsigned idx = (c >> 6)*16384 + (SWZ128((unsigned)(n*128 + (c & 63)*2)) >> 1);
        if (which) { g_wch[idx] = hi; g_wcl[idx] = lo; }
        else       { g_wuh[idx] = hi; g_wul[idx] = lo; }
    }
}

// ---------------- HMMA 2x2 up-conv (split-bf16, unchanged) ----------------
#define UPC_SMEM (98304 + 8704)
template<int DST>
__global__ __launch_bounds__(256, 2) void upconv_mma_kernel(
    const float* __restrict__ src, const float* __restrict__ bias,
    float* __restrict__ xout)
{
    extern __shared__ char smem[];
    const uint32_t sb = smem_u32(smem);
    float* in_s = (float*)(smem + 98304);

    const int t = threadIdx.x;
    const int lane = t & 31, w = t >> 5;
    const int px0 = (w & 1) * 32;
    const int n0  = (w >> 1) * 64;
    const int w0 = blockIdx.x * 64, h = blockIdx.y, b = blockIdx.z;

    const u16* __restrict__ wth = DST ? g_wch : g_wuh;
    const u16* __restrict__ wtl = DST ? g_wcl : g_wul;

#pragma unroll 1
    for (int half = 0; half < 4; half++) {
        int cb = half >> 1, sub = half & 1;
        int c0 = cb*64 + sub*32;
        {
            int c = t >> 3, pg = t & 7;
            const float* sp = &src[(((size_t)(b*CINC + c0 + c)*HUPC) + h)*HUPC + w0 + pg*8];
            float4 u0 = ((const float4*)sp)[0];
            float4 u1 = ((const float4*)sp)[1];
            float* dd = &in_s[c*68 + pg*8];
            dd[0]=u0.x; dd[1]=u0.y; dd[2]=u0.z; dd[3]=u0.w;
            dd[4]=u1.x; dd[5]=u1.y; dd[6]=u1.z; dd[7]=u1.w;
        }
        __syncthreads();
        {
            int px = t & 63, oct = t >> 6;
            float f[8];
#pragma unroll
            for (int i = 0; i < 8; i++) f[i] = in_s[(oct*8 + i)*68 + px];
            uint4 hv, lv; cvt_hilo8(f, hv, lv);
            unsigned sw = SWZ128((unsigned)(px*128 + (sub*32 + oct*8)*2));
            *(uint4*)(smem + cb*8192 + sw)         = hv;
            *(uint4*)(smem + 16384 + cb*8192 + sw) = lv;
        }
        __syncthreads();
    }

    float d[2][8][4];
#pragma unroll
    for (int mi = 0; mi < 2; mi++)
#pragma unroll
        for (int ni = 0; ni < 8; ni++)
#pragma unroll
            for (int r = 0; r < 4; r++) d[mi][ni][r] = 0.f;

#pragma unroll 1
    for (int cb = 0; cb < 2; cb++) {
        {
            const uint4* bhp = (const uint4*)(wth + cb*16384);
            const uint4* blp = (const uint4*)(wtl + cb*16384);
            uint4* dh = (uint4*)(smem + 32768);
            uint4* dl = (uint4*)(smem + 65536);
#pragma unroll
            for (int i = 0; i < 8; i++) { dh[t + i*256] = bhp[t + i*256]; dl[t + i*256] = blp[t + i*256]; }
        }
        __syncthreads();
        const uint32_t sah = sb + cb*8192;
        const uint32_t sal = sb + 16384 + cb*8192;
#pragma unroll
        for (int ks = 0; ks < 4; ks++) {
            uint32_t ah[2][4], al[2][4], bh[4][4], bl[4][4];
            const int arow  = lane & 15;
            const int acolb = ks*32 + (lane >> 4)*16;
            ldsm_x4(sah + SWZ128((px0 +      arow)*128 + acolb), ah[0]);
            ldsm_x4(sah + SWZ128((px0 + 16 + arow)*128 + acolb), ah[1]);
            ldsm_x4(sal + SWZ128((px0 +      arow)*128 + acolb), al[0]);
            ldsm_x4(sal + SWZ128((px0 + 16 + arow)*128 + acolb), al[1]);
            const int brow  = (lane & 7) + ((lane >> 4)*8);
            const int bcolb = ks*32 + ((lane >> 3) & 1)*16;
#pragma unroll
            for (int g = 0; g < 4; g++) {
                ldsm_x4(sb + 32768 + SWZ128((n0 + g*16 + brow)*128 + bcolb), bh[g]);
                ldsm_x4(sb + 65536 + SWZ128((n0 + g*16 + brow)*128 + bcolb), bl[g]);
            }
#pragma unroll
            for (int term = 0; term < 3; term++)
#pragma unroll
                for (int mi = 0; mi < 2; mi++)
#pragma unroll
                    for (int g = 0; g < 4; g++) {
                        const uint32_t* A = (term == 2) ? al[mi] : ah[mi];
                        const uint32_t* B = (term == 1) ? bl[g]  : bh[g];
                        mma_bf16(d[mi][g*2],     A, &B[0]);
                        mma_bf16(d[mi][g*2 + 1], A, &B[2]);
                    }
        }
        __syncthreads();
    }

    float* ep = (float*)smem;
    const int rr  = lane >> 2;
    const int rc2 = (lane & 3) * 2;
#pragma unroll
    for (int mi = 0; mi < 2; mi++)
#pragma unroll
    for (int ni = 0; ni < 8; ni++) {
        int n = n0 + (ni >> 1)*16 + (ni & 1)*8 + rc2;
#pragma unroll
        for (int hh = 0; hh < 2; hh++) {
            int px = px0 + mi*16 + rr + hh*8;
            *(float2*)&ep[px*260 + n] = make_float2(d[mi][ni][hh*2], d[mi][ni][hh*2 + 1]);
        }
    }
    __syncthreads();

    if (DST == 0) {
        int px = t >> 2, dk = t & 3;
        int dd = dk >> 1, k = dk & 1;
        size_t base = (((size_t)(b*RESOC + 2*h + dd)*RESOC) + 2*(w0 + px) + k)*CINC;
#pragma unroll
        for (int oct = 0; oct < 8; oct++) {
            float f[8];
#pragma unroll
            for (int i = 0; i < 8; i++)
                f[i] = ep[px*260 + (oct*8 + i)*4 + dk] + bias[oct*8 + i];
            uint4 hv, lv; cvt_hilo8(f, hv, lv);
            *(uint4*)&g_in_h[base + oct*8] = hv;
            *(uint4*)&g_in_l[base + oct*8] = lv;
        }
    } else {
        int o = t >> 2, dd = (t >> 1) & 1, half = t & 1;
        float bv = bias[o];
        size_t base = (((size_t)(b*COUTC + o)*RESOC) + 2*h + dd)*RESOC + 2*w0 + half*64;
#pragma unroll
        for (int g = 0; g < 16; g++) {
            int p0 = half*32 + g*2;
            float v0 = ep[ p0     *260 + o*4 + dd*2 + 0] + bv;
            float v1 = ep[ p0     *260 + o*4 + dd*2 + 1] + bv;
            float v2 = ep[(p0 + 1)*260 + o*4 + dd*2 + 0] + bv;
            float v3 = ep[(p0 + 1)*260 + o*4 + dd*2 + 1] + bv;
            *(float4*)&xout[base + g*4] = make_float4(v0, v1, v2, v3);
        }
    }
}

// ---------------- transpose from_down cm -> g_in_h/l ch 64..127 -----------
__global__ __launch_bounds__(256) void transpose_kernel(const float* __restrict__ fd) {
    __shared__ float s[64][33];
    int t = threadIdx.x;
    int xb = blockIdx.x, y = blockIdx.y, b = blockIdx.z;
#pragma unroll
    for (int i = 0; i < 8; i++) {
        int e = t + i*256;
        int c = e >> 5, px = e & 31;
        s[c][px] = fd[(((size_t)(b*64 + c)*RESOC) + y)*RESOC + xb*32 + px];
    }
    __syncthreads();
    int px = t >> 3, q = t & 7;
    float f[8];
#pragma unroll
    for (int i = 0; i < 8; i++) f[i] = s[q*8 + i][px];
    uint4 hv, lv; cvt_hilo8(f, hv, lv);
    size_t base = (((size_t)(b*RESOC + y)*RESOC) + xb*32 + px)*CINC + 64 + q*8;
    *(uint4*)&g_in_h[base] = hv;
    *(uint4*)&g_in_l[base] = lv;
}

// ---------------- HMMA 3x3 conv, A-strip resident, B via fragment LDG -----
// smem: A strips only (3 x 130 x 64ch hi/lo, swizzled) = 101376 B -> 2 CTAs/SM
#define CV_AH(s) ((s)*16896)
#define CV_AL(s) (50688 + (s)*16896)
#define CV_SMEM  101376

template<int MODE>
__global__ __launch_bounds__(256, 2) void conv_mma_kernel(
    const float* __restrict__ bias, float* __restrict__ xout)
{
    constexpr int CIN = (MODE == 1) ? 128 : 64;
    constexpr int NCB = CIN / 64;
    extern __shared__ char smem[];
    const uint32_t sb = smem_u32(smem);

    const int t = threadIdx.x;
    const int lane = t & 31, w = t >> 5;
    const int px0 = (w & 3) * 32;
    const int oh  = w >> 2;                 // oc half
    const int oc0 = oh * 32;
    const int x0 = blockIdx.x * 128, y = blockIdx.y, b = blockIdx.z;

    const u16* __restrict__ srch = (MODE == 1) ? g_in_h : g_x1h;
    const u16* __restrict__ srcl = (MODE == 1) ? g_in_l : g_x1l;
    const uint4* __restrict__ wfh = (const uint4*)((MODE == 1) ? g_w1fh : g_w2fh);
    const uint4* __restrict__ wfl = (const uint4*)((MODE == 1) ? g_w1fl : g_w2fl);

    float d[2][4][4];
#pragma unroll
    for (int mi = 0; mi < 2; mi++)
#pragma unroll
        for (int ni = 0; ni < 4; ni++)
#pragma unroll
            for (int r = 0; r < 4; r++) d[mi][ni][r] = 0.f;

#pragma unroll 1
    for (int cb = 0; cb < NCB; cb++) {
        // ---- stage A strips: 3 x 130 rows x 64 ch (hi/lo), swizzled
        {
            const uint4 z = make_uint4(0,0,0,0);
#pragma unroll 1
            for (int e = t; e < 3*130*8; e += 256) {
                int ri = e >> 3, i = e & 7;
                int s = ri / 130, row = ri % 130;
                int gy = y + s - 1, gx = x0 + row - 1;
                bool ok = (gy >= 0 && gy < 256 && gx >= 0 && gx < 256);
                uint4 hv = z, lv = z;
                if (ok) {
                    size_t off = (((size_t)(b*RESOC + gy)*RESOC) + gx)*CIN + cb*64 + i*8;
                    hv = *(const uint4*)(srch + off);
                    lv = *(const uint4*)(srcl + off);
                }
                unsigned sw = SWZ128((unsigned)(row*128 + i*16));
                *(uint4*)(smem + CV_AH(s) + sw) = hv;
                *(uint4*)(smem + CV_AL(s) + sw) = lv;
            }
        }
        __syncthreads();
        // ---- 9 taps off resident strips; B fragments direct from gmem (L1/L2)
#pragma unroll 1
        for (int tap = 0; tap < 9; tap++) {
            const int s = tap / 3, dx = tap % 3 - 1;
            const int gy = y + s - 1;
            if (gy < 0 || gy > 255) continue;     // uniform over CTA
            const uint32_t sah = sb + CV_AH(s);
            const uint32_t sal = sb + CV_AL(s);
            const int ar = px0 + (lane & 15) + 1 + dx;
            const unsigned wb0 = (unsigned)(((tap*NCB + cb)*2 + oh)*2)*128 + lane;
#pragma unroll
            for (int ks = 0; ks < 4; ks++) {
                uint32_t ah[2][4], al[2][4], bh[2][4], bl[2][4];
                // B fragments: one LDG.128 each
                *(uint4*)bh[0] = wfh[wb0        + ks*32];
                *(uint4*)bh[1] = wfh[wb0 + 128  + ks*32];
                *(uint4*)bl[0] = wfl[wb0        + ks*32];
                *(uint4*)bl[1] = wfl[wb0 + 128  + ks*32];
                const int acolb = ks*32 + (lane >> 4)*16;
                ldsm_x4(sah + SWZ128( ar      *128 + acolb), ah[0]);
                ldsm_x4(sah + SWZ128((ar + 16)*128 + acolb), ah[1]);
                ldsm_x4(sal + SWZ128( ar      *128 + acolb), al[0]);
                ldsm_x4(sal + SWZ128((ar + 16)*128 + acolb), al[1]);
#pragma unroll
                for (int term = 0; term < 3; term++)
#pragma unroll
                    for (int mi = 0; mi < 2; mi++)
#pragma unroll
                        for (int g = 0; g < 2; g++) {
                            const uint32_t* A = (term == 2) ? al[mi] : ah[mi];
                            const uint32_t* B = (term == 1) ? bl[g]  : bh[g];
                            mma_bf16(d[mi][g*2],     A, &B[0]);
                            mma_bf16(d[mi][g*2 + 1], A, &B[2]);
                        }
            }
        }
        __syncthreads();   // A strips safe to restage
    }

    const int rr  = lane >> 2;
    const int rc2 = (lane & 3) * 2;
#pragma unroll
    for (int mi = 0; mi < 2; mi++)
#pragma unroll
    for (int ni = 0; ni < 4; ni++) {
        int oc = oc0 + (ni >> 1)*16 + (ni & 1)*8 + rc2;
        float b0v = bias[oc], b1v = bias[oc + 1];
#pragma unroll
        for (int hh = 0; hh < 2; hh++) {
            int pxl = px0 + mi*16 + rr + hh*8;
            int x = x0 + pxl;
            float v0 = fmaxf(d[mi][ni][hh*2 + 0] + b0v, 0.f);
            float v1 = fmaxf(d[mi][ni][hh*2 + 1] + b1v, 0.f);
            if (MODE == 1) {
                size_t base = (((size_t)(b*RESOC + y)*RESOC) + x)*COUTC + oc;
                unsigned hi = bfpair(v0, v1);
                float l0 = v0 - bflo_f(hi), l1 = v1 - bfhi_f(hi);
                unsigned lo = bfpair(l0, l1);
                *(u32*)&g_x1h[base] = hi;
                *(u32*)&g_x1l[base] = lo;
            } else {
                size_t cm0 = (((size_t)(b*COUTC + oc)*RESOC) + y)*RESOC + x;
                size_t cm1 = cm0 + (size_t)RESOC*RESOC;
                float r0 = v0 + xout[cm0], r1 = v1 + xout[cm1];
                xout[cm0] = r0; xout[cm1] = r1;
                *(float2*)&g_xt[(((size_t)(b*RESOC + y)*RESOC) + x)*COUTC + oc] =
                    make_float2(r0, r1);
            }
        }
    }
}

// ---------------- fused point pipeline (persistent, B via fragment LDG) ---
#define PT_A1H 0
#define PT_A1L 8192
#define PT_HH  16384
#define PT_HL  49152
#define PT_IDX 81920
#define PT_SMEM (81920 + 512)
#define PT_TILES 6250

__global__ __launch_bounds__(256, 2) void points_kernel(
    const float* __restrict__ p,   const float* __restrict__ c_last,
    const float* __restrict__ bf1, const float* __restrict__ bf2,
    const float* __restrict__ bfc,
    float* __restrict__ fea, float* __restrict__ cout)
{
    extern __shared__ char smem[];
    const uint32_t sb = smem_u32(smem);
    int* idx_s = (int*)(smem + PT_IDX);

    const int t = threadIdx.x;
    const int lane = t & 31, wid = t >> 5;

    const uint4* __restrict__ w1fh = (const uint4*)g_pw1fh;
    const uint4* __restrict__ w1fl = (const uint4*)g_pw1fl;
    const uint4* __restrict__ w2fh = (const uint4*)g_pw2fh;
    const uint4* __restrict__ w2fl = (const uint4*)g_pw2fl;

    const int rr  = lane >> 2;
    const int rc2 = (lane & 3) * 2;

#pragma unroll 1
    for (int tile = blockIdx.x; tile < PT_TILES; tile += gridDim.x) {
        // ---- phase 1: sample v -> A1; stage c_last -> H kc2,3
        {
            int pt = t >> 2, part = t & 3;
            int g = tile*64 + pt;
            int b = g / NPTSC;
            float px = p[(size_t)g*3 + 0], py = p[(size_t)g*3 + 1];
            float ix = fminf(fmaxf(px*255.f, 0.f), 255.f);
            float iy = fminf(fmaxf(py*255.f, 0.f), 255.f);
            float x0f = floorf(ix), y0f = floorf(iy);
            int x0 = (int)x0f, y0i = (int)y0f;
            int x1 = min(x0 + 1, 255), y1 = min(y0i + 1, 255);
            float wx = ix - x0f, wy = iy - y0f;
            float w00 = (1.f-wx)*(1.f-wy), w01 = wx*(1.f-wy);
            float w10 = (1.f-wx)*wy,       w11 = wx*wy;
            const float* f00 = &g_xt[(((size_t)(b*RESOC + y0i)*RESOC) + x0)*COUTC + part*16];
            const float* f01 = &g_xt[(((size_t)(b*RESOC + y0i)*RESOC) + x1)*COUTC + part*16];
            const float* f10 = &g_xt[(((size_t)(b*RESOC + y1 )*RESOC) + x0)*COUTC + part*16];
            const float* f11 = &g_xt[(((size_t)(b*RESOC + y1 )*RESOC) + x1)*COUTC + part*16];
#pragma unroll
            for (int i = 0; i < 4; i++) {
                float4 a = *(const float4*)&f00[i*4];
                float4 bq = *(const float4*)&f01[i*4];
                float4 cq = *(const float4*)&f10[i*4];
                float4 dq = *(const float4*)&f11[i*4];
                float r0 = a.x*w00 + bq.x*w01 + cq.x*w10 + dq.x*w11;
                float r1 = a.y*w00 + bq.y*w01 + cq.y*w10 + dq.y*w11;
                float r2 = a.z*w00 + bq.z*w01 + cq.z*w10 + dq.z*w11;
                float r3 = a.w*w00 + bq.w*w01 + cq.w*w10 + dq.w*w11;
                unsigned h0 = bfpair(r0, r1), h1 = bfpair(r2, r3);
                float l0 = r0 - bflo_f(h0), l1 = r1 - bfhi_f(h0);
                float l2 = r2 - bflo_f(h1), l3 = r3 - bfhi_f(h1);
                unsigned q0 = bfpair(l0, l1), q1 = bfpair(l2, l3);
                unsigned sw = SWZ128((unsigned)(pt*128 + part*32 + (i >> 1)*16)) + (i & 1)*8;
                *(uint2*)(smem + PT_A1H + sw) = make_uint2(h0, h1);
                *(uint2*)(smem + PT_A1L + sw) = make_uint2(q0, q1);
            }
            if (part == 0) {
                int gx = min(max((int)(px*256.f), 0), 255);
                int gy = min(max((int)(py*256.f), 0), 255);
                int cell = gy*256 + gx;
                idx_s[pt] = cell;
                atomicAdd(&g_cnt[b*65536 + cell], 1u);
            }
            const float* cls = c_last + (size_t)g*128 + part*32;
            int kc = 2 + (part >> 1);
#pragma unroll
            for (int grp = 0; grp < 4; grp++) {
                float f[8];
                float4 u0 = ((const float4*)cls)[grp*2];
                float4 u1 = ((const float4*)cls)[grp*2 + 1];
                f[0]=u0.x; f[1]=u0.y; f[2]=u0.z; f[3]=u0.w;
                f[4]=u1.x; f[5]=u1.y; f[6]=u1.z; f[7]=u1.w;
                uint4 hv, lv; cvt_hilo8(f, hv, lv);
                int col = (part*32 + grp*8) & 63;
                unsigned sw = SWZ128((unsigned)(pt*128 + col*2));
                *(uint4*)(smem + PT_HH + kc*8192 + sw) = hv;
                *(uint4*)(smem + PT_HL + kc*8192 + sw) = lv;
            }
        }
        __syncthreads();

        // ---- GEMM1: h1[64,128] = relu(v @ Wf1^T + bf1) -> H kc0,1
        {
            const int pt0 = (wid & 1) * 32;
            const int oh1 = wid >> 1;          // j-quarter 0..3
            const int j0  = oh1 * 32;
            float d[2][4][4];
#pragma unroll
            for (int mi = 0; mi < 2; mi++)
#pragma unroll
                for (int ni = 0; ni < 4; ni++)
#pragma unroll
                    for (int r = 0; r < 4; r++) d[mi][ni][r] = 0.f;

            const unsigned wb0 = (unsigned)(oh1*2)*128 + lane;
#pragma unroll
            for (int ks = 0; ks < 4; ks++) {
                uint32_t ah[2][4], al[2][4], bh[2][4], bl[2][4];
                *(uint4*)bh[0] = w1fh[wb0       + ks*32];
                *(uint4*)bh[1] = w1fh[wb0 + 128 + ks*32];
                *(uint4*)bl[0] = w1fl[wb0       + ks*32];
                *(uint4*)bl[1] = w1fl[wb0 + 128 + ks*32];
                const int arow  = lane & 15;
                const int acolb = ks*32 + (lane >> 4)*16;
                ldsm_x4(sb + PT_A1H + SWZ128((pt0 +      arow)*128 + acolb), ah[0]);
                ldsm_x4(sb + PT_A1H + SWZ128((pt0 + 16 + arow)*128 + acolb), ah[1]);
                ldsm_x4(sb + PT_A1L + SWZ128((pt0 +      arow)*128 + acolb), al[0]);
                ldsm_x4(sb + PT_A1L + SWZ128((pt0 + 16 + arow)*128 + acolb), al[1]);
#pragma unroll
                for (int term = 0; term < 3; term++)
#pragma unroll
                    for (int mi = 0; mi < 2; mi++)
#pragma unroll
                        for (int g = 0; g < 2; g++) {
                            const uint32_t* A = (term == 2) ? al[mi] : ah[mi];
                            const uint32_t* B = (term == 1) ? bl[g]  : bh[g];
                            mma_bf16(d[mi][g*2],     A, &B[0]);
                            mma_bf16(d[mi][g*2 + 1], A, &B[2]);
                        }
            }
#pragma unroll
            for (int mi = 0; mi < 2; mi++)
#pragma unroll
            for (int ni = 0; ni < 4; ni++) {
                int j = j0 + (ni >> 1)*16 + (ni & 1)*8 + rc2;
                float b0v = bf1[j], b1v = bf1[j + 1];
                int kc = j >> 6, col = j & 63;
#pragma unroll
                for (int hh = 0; hh < 2; hh++) {
                    int pt = pt0 + mi*16 + rr + hh*8;
                    float v0 = fmaxf(d[mi][ni][hh*2 + 0] + b0v, 0.f);
                    float v1 = fmaxf(d[mi][ni][hh*2 + 1] + b1v, 0.f);
                    unsigned hi = bfpair(v0, v1);
                    float l0 = v0 - bflo_f(hi), l1 = v1 - bfhi_f(hi);
                    unsigned lo = bfpair(l0, l1);
                    unsigned sw = SWZ128((unsigned)(pt*128 + (col & ~7)*2)) + (col & 7)*2;
                    *(u32*)(smem + PT_HH + kc*8192 + sw) = hi;
                    *(u32*)(smem + PT_HL + kc*8192 + sw) = lo;
                }
            }
        }
        __syncthreads();

        // ---- GEMM2: c[64,64] = Hcat @ W2cat^T (+bf2+bfc); write + scatter
        {
            const int m0 = (wid & 3) * 16;
            const int oh2 = wid >> 2;          // 0/1
            const int o0 = oh2 * 32;
            float d[4][4];
#pragma unroll
            for (int ni = 0; ni < 4; ni++)
#pragma unroll
                for (int r = 0; r < 4; r++) d[ni][r] = 0.f;

#pragma unroll 1
            for (int ks = 0; ks < 16; ks++) {
                const int kc = ks >> 2, kk = ks & 3;
                uint32_t ah[4], al[4], bh[2][4], bl[2][4];
                const unsigned wb = (unsigned)(((kc*2 + oh2)*2)*4 + kk)*32 + lane;
                *(uint4*)bh[0] = w2fh[wb];
                *(uint4*)bh[1] = w2fh[wb + 128];
                *(uint4*)bl[0] = w2fl[wb];
                *(uint4*)bl[1] = w2fl[wb + 128];
                const int arow  = lane & 15;
                const int acolb = kk*32 + (lane >> 4)*16;
                ldsm_x4(sb + PT_HH + kc*8192 + SWZ128((m0 + arow)*128 + acolb), ah);
                ldsm_x4(sb + PT_HL + kc*8192 + SWZ128((m0 + arow)*128 + acolb), al);
#pragma unroll
                for (int term = 0; term < 3; term++)
#pragma unroll
                    for (int g = 0; g < 2; g++) {
                        const uint32_t* A = (term == 2) ? al : ah;
                        const uint32_t* B = (term == 1) ? bl[g] : bh[g];
                        mma_bf16(d[g*2],     A, &B[0]);
                        mma_bf16(d[g*2 + 1], A, &B[2]);
                    }
            }
#pragma unroll
            for (int ni = 0; ni < 4; ni++) {
                int o = o0 + (ni >> 1)*16 + (ni & 1)*8 + rc2;
                float b0v = bf2[o] + bfc[o], b1v = bf2[o + 1] + bfc[o + 1];
#pragma unroll
                for (int hh = 0; hh < 2; hh++) {
                    int pt = m0 + rr + hh*8;
                    int g = tile*64 + pt;
                    int b = g / NPTSC;
                    int cell = idx_s[pt];
                    float cv0 = d[ni][hh*2 + 0] + b0v;
                    float cv1 = d[ni][hh*2 + 1] + b1v;
                    *(float2*)&cout[(size_t)g*64 + o] = make_float2(cv0, cv1);
                    atomicAdd(&fea[((size_t)(b*COUTC + o    ))*65536 + cell], cv0);
                    atomicAdd(&fea[((size_t)(b*COUTC + o + 1))*65536 + cell], cv1);
                }
            }
        }
        __syncthreads();
    }
}

// ---------------- scatter-mean finalize -----------------------------------
__global__ __launch_bounds__(256) void finalize_kernel(float* __restrict__ fea) {
    size_t i = (size_t)blockIdx.x * 256 + threadIdx.x;
    size_t stride = (size_t)gridDim.x * 256;
    for (size_t e = i; e < (size_t)BB*COUTC*RESOC*RESOC; e += stride) {
        unsigned cell = (unsigned)(e & 65535u);
        unsigned b = (unsigned)(e >> 22);
        unsigned c = g_cnt[b*65536 + cell];
        fea[e] *= 1.f / (float)(c > 1u ? c : 1u);
    }
}

// ---------------- launch ---------------------------------------------------
extern "C" void kernel_launch(void* const* d_in, const int* in_sizes, int n_in,
                              void* d_out, int out_size) {
    (void)in_sizes; (void)n_in; (void)out_size;
    const float* p         = (const float*)d_in[0];
    const float* from_up   = (const float*)d_in[1];
    const float* from_down = (const float*)d_in[2];
    const float* x_after   = (const float*)d_in[3];
    const float* c_last    = (const float*)d_in[4];
    const float* W_up      = (const float*)d_in[5];
    const float* b_up      = (const float*)d_in[6];
    const float* W1        = (const float*)d_in[7];
    const float* b1        = (const float*)d_in[8];
    const float* W2        = (const float*)d_in[9];
    const float* b2        = (const float*)d_in[10];
    const float* Wc        = (const float*)d_in[11];
    const float* bc        = (const float*)d_in[12];
    const float* Wf1       = (const float*)d_in[13];
    const float* bf1       = (const float*)d_in[14];
    const float* Wf2       = (const float*)d_in[15];
    const float* bf2       = (const float*)d_in[16];
    const float* Wfc       = (const float*)d_in[17];
    const float* bfc       = (const float*)d_in[18];

    float* out  = (float*)d_out;
    float* fea  = out;                        // (B,64,256,256)
    float* xout = out + (size_t)16777216;     // (B,64,256,256)
    float* cout = out + (size_t)33554432;     // (B,NPTS,64)

    static cudaStream_t s1 = nullptr, s2 = nullptr, s3 = nullptr;
    static cudaEvent_t eStart = nullptr, eW = nullptr, eZero = nullptr,
                       eUpc1 = nullptr, eTr = nullptr;
    if (!s1) {
        cudaStreamCreateWithFlags(&s1, cudaStreamNonBlocking);
        cudaStreamCreateWithFlags(&s2, cudaStreamNonBlocking);
        cudaStreamCreateWithFlags(&s3, cudaStreamNonBlocking);
        cudaEventCreateWithFlags(&eStart, cudaEventDisableTiming);
        cudaEventCreateWithFlags(&eW,     cudaEventDisableTiming);
        cudaEventCreateWithFlags(&eZero,  cudaEventDisableTiming);
        cudaEventCreateWithFlags(&eUpc1,  cudaEventDisableTiming);
        cudaEventCreateWithFlags(&eTr,    cudaEventDisableTiming);
        cudaFuncSetAttribute(points_kernel, cudaFuncAttributeMaxDynamicSharedMemorySize, PT_SMEM);
        cudaFuncSetAttribute(upconv_mma_kernel<0>, cudaFuncAttributeMaxDynamicSharedMemorySize, UPC_SMEM);
        cudaFuncSetAttribute(upconv_mma_kernel<1>, cudaFuncAttributeMaxDynamicSharedMemorySize, UPC_SMEM);
        cudaFuncSetAttribute(conv_mma_kernel<1>, cudaFuncAttributeMaxDynamicSharedMemorySize, CV_SMEM);
        cudaFuncSetAttribute(conv_mma_kernel<2>, cudaFuncAttributeMaxDynamicSharedMemorySize, CV_SMEM);
    }

    // fork point on the (possibly capturing) origin stream
    cudaEventRecord(eStart, 0);

    // origin: weight convert, then upconv0 (conv1's critical path)
    wconv_kernel<<<784, 256>>>(W1, W2, Wf1, Wf2, Wfc, W_up, Wc);
    cudaEventRecord(eW, 0);
    upconv_mma_kernel<0><<<dim3(2, 128, 4), 256, UPC_SMEM>>>(from_up, b_up, nullptr);

    // s1: zero fea + counts (needed only by points)
    cudaStreamWaitEvent(s1, eStart, 0);
    zero_kernel<<<2048, 256, 0, s1>>>(fea);
    cudaEventRecord(eZero, s1);

    // s2: upconv1 -> xout residual (needed only by conv2 epilogue)
    cudaStreamWaitEvent(s2, eW, 0);
    upconv_mma_kernel<1><<<dim3(2, 128, 4), 256, UPC_SMEM, s2>>>(x_after, bc, xout);
    cudaEventRecord(eUpc1, s2);

    // s3: transpose from_down (needed by conv1)
    cudaStreamWaitEvent(s3, eStart, 0);
    transpose_kernel<<<dim3(8, 256, 4), 256, 0, s3>>>(from_down);
    cudaEventRecord(eTr, s3);

    // origin: conv1 after upconv0 (ordered) + transpose (event)
    cudaStreamWaitEvent(0, eTr, 0);
    conv_mma_kernel<1><<<dim3(2, 256, 4), 256, CV_SMEM>>>(b1, nullptr);

    // conv2 after conv1 (ordered) + upconv1 (event)
    cudaStreamWaitEvent(0, eUpc1, 0);
    conv_mma_kernel<2><<<dim3(2, 256, 4), 256, CV_SMEM>>>(b2, xout);

    // points after conv2 (ordered) + zero (event)
    cudaStreamWaitEvent(0, eZero, 0);
    points_kernel<<<296, 256, PT_SMEM>>>(p, c_last, bf1, bf2, bfc, fea, cout);
    finalize_kernel<<<8192, 256>>>(fea);
}

// round 15
// speedup vs baseline: 1.3739x; 1.0115x over previous
#include <cuda_runtime.h>
#include <cstdint>

#define BB    4
#define CINC  128
#define COUTC 64
#define HUPC  128
#define RESOC 256
#define NPTSC 100000

typedef unsigned long long ull;
typedef unsigned short u16;
typedef unsigned int u32;

// ---------------- scratch (static device globals; no allocs allowed) -------
__device__ __align__(16) u16 g_in_h[(size_t)BB*RESOC*RESOC*CINC];   // 64 MB bf16 hi
__device__ __align__(16) u16 g_in_l[(size_t)BB*RESOC*RESOC*CINC];   // 64 MB bf16 lo
__device__ __align__(16) u16 g_x1h [(size_t)BB*RESOC*RESOC*COUTC];  // 32 MB
__device__ __align__(16) u16 g_x1l [(size_t)BB*RESOC*RESOC*COUTC];  // 32 MB
__device__ float g_xt [(size_t)BB*RESOC*RESOC*COUTC];               // 64 MB f32 ch-last x
__device__ unsigned g_cnt [BB*RESOC*RESOC];
// fragment-major conv weights: uint4 per (tap,cb,oh,g,ks,lane)
__device__ __align__(16) u16 g_w1fh[73728];
__device__ __align__(16) u16 g_w1fl[73728];
__device__ __align__(16) u16 g_w2fh[36864];
__device__ __align__(16) u16 g_w2fl[36864];
// fragment-major point-MLP weights
__device__ __align__(16) u16 g_pw1fh[8192];   // Wf1: (oh4,g2,ks4,lane32)
__device__ __align__(16) u16 g_pw1fl[8192];
__device__ __align__(16) u16 g_pw2fh[16384];  // W2cat: (kc4,oh2,g2,kk4,lane32)
__device__ __align__(16) u16 g_pw2fl[16384];
// fragment-major upconv weights: (cb2, ng16, ks4, lane32) uint4
__device__ __align__(16) u16 g_wufh[32768];
__device__ __align__(16) u16 g_wufl[32768];
__device__ __align__(16) u16 g_wcfh[32768];
__device__ __align__(16) u16 g_wcfl[32768];

// ---------------- mma helpers ---------------------------------------------
__device__ __forceinline__ uint32_t smem_u32(const void* p) {
    uint32_t a;
    asm("{ .reg .u64 t; cvta.to.shared.u64 t, %1; cvt.u32.u64 %0, t; }" : "=r"(a) : "l"(p));
    return a;
}
#define SWZ128(off) ((off) ^ (((off) >> 3) & 0x70))

__device__ __forceinline__ void ldsm_x4(uint32_t addr, uint32_t* r) {
    asm volatile("ldmatrix.sync.aligned.m8n8.x4.shared.b16 {%0,%1,%2,%3}, [%4];"
        : "=r"(r[0]), "=r"(r[1]), "=r"(r[2]), "=r"(r[3]) : "r"(addr));
}
__device__ __forceinline__ void mma_bf16(float* d, const uint32_t* a, const uint32_t* b) {
    asm volatile("mma.sync.aligned.m16n8k16.row.col.f32.bf16.bf16.f32 "
        "{%0,%1,%2,%3}, {%4,%5,%6,%7}, {%8,%9}, {%0,%1,%2,%3};"
        : "+f"(d[0]), "+f"(d[1]), "+f"(d[2]), "+f"(d[3])
        : "r"(a[0]), "r"(a[1]), "r"(a[2]), "r"(a[3]), "r"(b[0]), "r"(b[1]));
}

// bf16 split helpers
__device__ __forceinline__ unsigned bfpair(float lo_e, float hi_e) {
    unsigned r; asm("cvt.rn.bf16x2.f32 %0, %1, %2;" : "=r"(r) : "f"(hi_e), "f"(lo_e)); return r;
}
__device__ __forceinline__ float bflo_f(unsigned w) { return __uint_as_float(w << 16); }
__device__ __forceinline__ float bfhi_f(unsigned w) { return __uint_as_float(w & 0xffff0000u); }

__device__ __forceinline__ void cvt_hilo8(const float* f, uint4& hv, uint4& lv) {
    unsigned h0 = bfpair(f[0], f[1]);
    unsigned h1 = bfpair(f[2], f[3]);
    unsigned h2 = bfpair(f[4], f[5]);
    unsigned h3 = bfpair(f[6], f[7]);
    hv = make_uint4(h0, h1, h2, h3);
    float l0 = f[0] - bflo_f(h0), l1 = f[1] - bfhi_f(h0);
    float l2 = f[2] - bflo_f(h1), l3 = f[3] - bfhi_f(h1);
    float l4 = f[4] - bflo_f(h2), l5 = f[5] - bfhi_f(h2);
    float l6 = f[6] - bflo_f(h3), l7 = f[7] - bfhi_f(h3);
    lv = make_uint4(bfpair(l0, l1), bfpair(l2, l3), bfpair(l4, l5), bfpair(l6, l7));
}

// fragment element index inside a (16n x 16k) uint4 fragment
__device__ __forceinline__ unsigned frag_elem(int n16, int k16) {
    int lane = (n16 & 7)*4 + ((k16 & 7) >> 1);
    int jj = ((n16 >> 3) << 1) | ((k16 >> 3) & 1);
    int e = k16 & 1;
    return (unsigned)(lane*8 + jj*2 + e);
}

// ---------------- zero fea + counts ---------------------------------------
__global__ __launch_bounds__(256) void zero_kernel(float* __restrict__ fea) {
    size_t i = (size_t)blockIdx.x * 256 + threadIdx.x;
    size_t stride = (size_t)gridDim.x * 256;
    float4 z4 = make_float4(0.f, 0.f, 0.f, 0.f);
    for (size_t e = i; e < (size_t)BB*COUTC*RESOC*RESOC/4; e += stride)
        ((float4*)fea)[e] = z4;
    for (size_t e = i; e < BB*RESOC*RESOC/4; e += stride)
        ((uint4*)g_cnt)[e] = make_uint4(0u,0u,0u,0u);
}

// ---------------- weight pre-convert --------------------------------------
__global__ __launch_bounds__(256) void wconv_kernel(
    const float* __restrict__ W1, const float* __restrict__ W2,
    const float* __restrict__ Wf1, const float* __restrict__ Wf2,
    const float* __restrict__ Wfc, const float* __restrict__ W_up,
    const float* __restrict__ Wc)
{
    int t = blockIdx.x * 256 + threadIdx.x;
    if (t < 73728) {
        int tap = t % 9, c = (t / 9) % 128, o = t / 1152;
        float f = W1[t];
        u16 hi = (u16)(bfpair(f, 0.f) & 0xffff);
        float lf = f - bflo_f(hi);
        u16 lo = (u16)(bfpair(lf, 0.f) & 0xffff);
        int cb = c >> 6, ch = c & 63;
        int oh = o >> 5, g = (o >> 4) & 1;
        int ks = ch >> 4;
        unsigned idx4 = (unsigned)((((tap*2 + cb)*2 + oh)*2 + g)*4 + ks)*32;
        unsigned off = idx4*8 + frag_elem(o & 15, ch & 15);
        g_w1fh[off] = hi; g_w1fl[off] = lo;
    } else if (t < 110592) {
        int t2 = t - 73728;
        int tap = t2 % 9, c = (t2 / 9) % 64, o = t2 / 576;
        float f = W2[t2];
        u16 hi = (u16)(bfpair(f, 0.f) & 0xffff);
        float lf = f - bflo_f(hi);
        u16 lo = (u16)(bfpair(lf, 0.f) & 0xffff);
        int oh = o >> 5, g = (o >> 4) & 1;
        int ks = c >> 4;
        unsigned idx4 = (unsigned)(((tap*2 + oh)*2 + g)*4 + ks)*32;
        unsigned off = idx4*8 + frag_elem(o & 15, c & 15);
        g_w2fh[off] = hi; g_w2fl[off] = lo;
    } else if (t < 118784) {
        int e = t - 110592;
        int j = e >> 6, k = e & 63;
        float f = Wf1[j*64 + k];
        u16 hi = (u16)(bfpair(f, 0.f) & 0xffff);
        float lf = f - bflo_f(hi);
        u16 lo = (u16)(bfpair(lf, 0.f) & 0xffff);
        int oh = j >> 5, g = (j >> 4) & 1;
        int ks = k >> 4;
        unsigned idx4 = (unsigned)((oh*2 + g)*4 + ks)*32;
        unsigned off = idx4*8 + frag_elem(j & 15, k & 15);
        g_pw1fh[off] = hi; g_pw1fl[off] = lo;
    } else if (t < 135168) {
        int e = t - 118784;
        int which = e >> 13;           // 0: Wf2, 1: Wfc
        int e2 = e & 8191;
        int o = e2 >> 7, k = e2 & 127;
        float f = which ? Wfc[o*128 + k] : Wf2[o*128 + k];
        u16 hi = (u16)(bfpair(f, 0.f) & 0xffff);
        float lf = f - bflo_f(hi);
        u16 lo = (u16)(bfpair(lf, 0.f) & 0xffff);
        int kc = which*2 + (k >> 6);
        int kl64 = k & 63;
        int oh = o >> 5, g = (o >> 4) & 1;
        int kk = kl64 >> 4;
        unsigned idx4 = (unsigned)(((kc*2 + oh)*2 + g)*4 + kk)*32;
        unsigned off = idx4*8 + frag_elem(o & 15, kl64 & 15);
        g_pw2fh[off] = hi; g_pw2fl[off] = lo;
    } else if (t < 135168 + 65536) {
        int e = t - 135168;
        int which = e >> 15;           // 0: W_up, 1: Wc
        int e2 = e & 32767;            // c*256 + n
        int c = e2 >> 8, n = e2 & 255;
        float f = which ? Wc[e2] : W_up[e2];
        u16 hi = (u16)(bfpair(f, 0.f) & 0xffff);
        float lf = f - bflo_f(hi);
        u16 lo = (u16)(bfpair(lf, 0.f) & 0xffff);
        int cb = c >> 6, ch = c & 63;
        int ng = n >> 4;
        int ks = ch >> 4;
        unsigned idx4 = (unsigned)((cb*16 + ng)*4 + ks)*32;
        unsigned off = idx4*8 + frag_elem(n & 15, ch & 15);
        if (which) { g_wcfh[off] = hi; g_wcfl[off] = lo; }
        else       { g_wufh[off] = hi; g_wufl[off] = lo; }
    }
}

// ---------------- HMMA 2x2 up-conv (split-bf16, fragment-major B) ---------
// smem: Ahi cb0 @0, cb1 @8192; Alo cb0 @16384, cb1 @24576; in_s f32 [128][68] @32768.
// Epilogue f32 [64][260] (66560 B) reuses from 0.
#define UPC_INS 32768
#define UPC_SMEM (32768 + 34816)
template<int DST>
__global__ __launch_bounds__(256, 2) void upconv_mma_kernel(
    const float* __restrict__ src, const float* __restrict__ bias,
    float* __restrict__ xout)
{
    extern __shared__ char smem[];
    const uint32_t sb = smem_u32(smem);
    float* in_s = (float*)(smem + UPC_INS);

    const int t = threadIdx.x;
    const int lane = t & 31, w = t >> 5;
    const int px0 = (w & 1) * 32;
    const int n0  = (w >> 1) * 64;
    const int w0 = blockIdx.x * 64, h = blockIdx.y, b = blockIdx.z;

    const uint4* __restrict__ wfh = (const uint4*)(DST ? g_wcfh : g_wufh);
    const uint4* __restrict__ wfl = (const uint4*)(DST ? g_wcfl : g_wufl);

    // ---- stage all of A: 128 ch x 64 px f32 -> in_s (one pass, one sync)
    {
        int c = t >> 1, pg = t & 1;
        const float* sp = &src[(((size_t)(b*CINC + c)*HUPC) + h)*HUPC + w0 + pg*32];
        float* dd = &in_s[c*68 + pg*32];
#pragma unroll
        for (int i = 0; i < 8; i++)
            ((float4*)dd)[i] = ((const float4*)sp)[i];
    }
    __syncthreads();
    // ---- convert to bf16 hi/lo swizzled A tiles
    {
        int px = t & 63, oct = t >> 6;
#pragma unroll
        for (int sub = 0; sub < 4; sub++) {
            int c0 = sub*32 + oct*8;
            float f[8];
#pragma unroll
            for (int i = 0; i < 8; i++) f[i] = in_s[(c0 + i)*68 + px];
            uint4 hv, lv; cvt_hilo8(f, hv, lv);
            int cb = c0 >> 6, ch = c0 & 63;
            unsigned sw = SWZ128((unsigned)(px*128 + ch*2));
            *(uint4*)(smem + cb*8192 + sw)         = hv;
            *(uint4*)(smem + 16384 + cb*8192 + sw) = lv;
        }
    }
    __syncthreads();

    float d[2][8][4];
#pragma unroll
    for (int mi = 0; mi < 2; mi++)
#pragma unroll
        for (int ni = 0; ni < 8; ni++)
#pragma unroll
            for (int r = 0; r < 4; r++) d[mi][ni][r] = 0.f;

    const int ngb = n0 >> 4;
#pragma unroll 1
    for (int cb = 0; cb < 2; cb++) {
        const uint32_t sah = sb + cb*8192;
        const uint32_t sal = sb + 16384 + cb*8192;
#pragma unroll
        for (int ks = 0; ks < 4; ks++) {
            uint32_t ah[2][4], al[2][4], bh[4][4], bl[4][4];
#pragma unroll
            for (int g = 0; g < 4; g++) {
                unsigned wb = (unsigned)((cb*16 + ngb + g)*4 + ks)*32 + lane;
                *(uint4*)bh[g] = wfh[wb];
                *(uint4*)bl[g] = wfl[wb];
            }
            const int arow  = lane & 15;
            const int acolb = ks*32 + (lane >> 4)*16;
            ldsm_x4(sah + SWZ128((px0 +      arow)*128 + acolb), ah[0]);
            ldsm_x4(sah + SWZ128((px0 + 16 + arow)*128 + acolb), ah[1]);
            ldsm_x4(sal + SWZ128((px0 +      arow)*128 + acolb), al[0]);
            ldsm_x4(sal + SWZ128((px0 + 16 + arow)*128 + acolb), al[1]);
#pragma unroll
            for (int term = 0; term < 3; term++)
#pragma unroll
                for (int mi = 0; mi < 2; mi++)
#pragma unroll
                    for (int g = 0; g < 4; g++) {
                        const uint32_t* A = (term == 2) ? al[mi] : ah[mi];
                        const uint32_t* B = (term == 1) ? bl[g]  : bh[g];
                        mma_bf16(d[mi][g*2],     A, &B[0]);
                        mma_bf16(d[mi][g*2 + 1], A, &B[2]);
                    }
        }
    }
    __syncthreads();   // A/in_s dead; reuse smem for epilogue

    float* ep = (float*)smem;
    const int rr  = lane >> 2;
    const int rc2 = (lane & 3) * 2;
#pragma unroll
    for (int mi = 0; mi < 2; mi++)
#pragma unroll
    for (int ni = 0; ni < 8; ni++) {
        int n = n0 + (ni >> 1)*16 + (ni & 1)*8 + rc2;
#pragma unroll
        for (int hh = 0; hh < 2; hh++) {
            int px = px0 + mi*16 + rr + hh*8;
            *(float2*)&ep[px*260 + n] = make_float2(d[mi][ni][hh*2], d[mi][ni][hh*2 + 1]);
        }
    }
    __syncthreads();

    if (DST == 0) {
        int px = t >> 2, dk = t & 3;
        int dd = dk >> 1, k = dk & 1;
        size_t base = (((size_t)(b*RESOC + 2*h + dd)*RESOC) + 2*(w0 + px) + k)*CINC;
#pragma unroll
        for (int oct = 0; oct < 8; oct++) {
            float f[8];
#pragma unroll
            for (int i = 0; i < 8; i++)
                f[i] = ep[px*260 + (oct*8 + i)*4 + dk] + bias[oct*8 + i];
            uint4 hv, lv; cvt_hilo8(f, hv, lv);
            *(uint4*)&g_in_h[base + oct*8] = hv;
            *(uint4*)&g_in_l[base + oct*8] = lv;
        }
    } else {
        int o = t >> 2, dd = (t >> 1) & 1, half = t & 1;
        float bv = bias[o];
        size_t base = (((size_t)(b*COUTC + o)*RESOC) + 2*h + dd)*RESOC + 2*w0 + half*64;
#pragma unroll
        for (int g = 0; g < 16; g++) {
            int p0 = half*32 + g*2;
            float v0 = ep[ p0     *260 + o*4 + dd*2 + 0] + bv;
            float v1 = ep[ p0     *260 + o*4 + dd*2 + 1] + bv;
            float v2 = ep[(p0 + 1)*260 + o*4 + dd*2 + 0] + bv;
            float v3 = ep[(p0 + 1)*260 + o*4 + dd*2 + 1] + bv;
            *(float4*)&xout[base + g*4] = make_float4(v0, v1, v2, v3);
        }
    }
}

// ---------------- transpose from_down cm -> g_in_h/l ch 64..127 -----------
__global__ __launch_bounds__(256) void transpose_kernel(const float* __restrict__ fd) {
    __shared__ float s[64][33];
    int t = threadIdx.x;
    int xb = blockIdx.x, y = blockIdx.y, b = blockIdx.z;
#pragma unroll
    for (int i = 0; i < 8; i++) {
        int e = t + i*256;
        int c = e >> 5, px = e & 31;
        s[c][px] = fd[(((size_t)(b*64 + c)*RESOC) + y)*RESOC + xb*32 + px];
    }
    __syncthreads();
    int px = t >> 3, q = t & 7;
    float f[8];
#pragma unroll
    for (int i = 0; i < 8; i++) f[i] = s[q*8 + i][px];
    uint4 hv, lv; cvt_hilo8(f, hv, lv);
    size_t base = (((size_t)(b*RESOC + y)*RESOC) + xb*32 + px)*CINC + 64 + q*8;
    *(uint4*)&g_in_h[base] = hv;
    *(uint4*)&g_in_l[base] = lv;
}

// ---------------- HMMA 3x3 conv, A-strip resident, B via fragment LDG -----
#define CV_AH(s) ((s)*16896)
#define CV_AL(s) (50688 + (s)*16896)
#define CV_SMEM  101376

template<int MODE>
__global__ __launch_bounds__(256, 2) void conv_mma_kernel(
    const float* __restrict__ bias, float* __restrict__ xout)
{
    constexpr int CIN = (MODE == 1) ? 128 : 64;
    constexpr int NCB = CIN / 64;
    extern __shared__ char smem[];
    const uint32_t sb = smem_u32(smem);

    const int t = threadIdx.x;
    const int lane = t & 31, w = t >> 5;
    const int px0 = (w & 3) * 32;
    const int oh  = w >> 2;
    const int oc0 = oh * 32;
    const int x0 = blockIdx.x * 128, y = blockIdx.y, b = blockIdx.z;

    const u16* __restrict__ srch = (MODE == 1) ? g_in_h : g_x1h;
    const u16* __restrict__ srcl = (MODE == 1) ? g_in_l : g_x1l;
    const uint4* __restrict__ wfh = (const uint4*)((MODE == 1) ? g_w1fh : g_w2fh);
    const uint4* __restrict__ wfl = (const uint4*)((MODE == 1) ? g_w1fl : g_w2fl);

    float d[2][4][4];
#pragma unroll
    for (int mi = 0; mi < 2; mi++)
#pragma unroll
        for (int ni = 0; ni < 4; ni++)
#pragma unroll
            for (int r = 0; r < 4; r++) d[mi][ni][r] = 0.f;

#pragma unroll 1
    for (int cb = 0; cb < NCB; cb++) {
        {
            const uint4 z = make_uint4(0,0,0,0);
#pragma unroll 1
            for (int e = t; e < 3*130*8; e += 256) {
                int ri = e >> 3, i = e & 7;
                int s = ri / 130, row = ri % 130;
                int gy = y + s - 1, gx = x0 + row - 1;
                bool ok = (gy >= 0 && gy < 256 && gx >= 0 && gx < 256);
                uint4 hv = z, lv = z;
                if (ok) {
                    size_t off = (((size_t)(b*RESOC + gy)*RESOC) + gx)*CIN + cb*64 + i*8;
                    hv = *(const uint4*)(srch + off);
                    lv = *(const uint4*)(srcl + off);
                }
                unsigned sw = SWZ128((unsigned)(row*128 + i*16));
                *(uint4*)(smem + CV_AH(s) + sw) = hv;
                *(uint4*)(smem + CV_AL(s) + sw) = lv;
            }
        }
        __syncthreads();
#pragma unroll 1
        for (int tap = 0; tap < 9; tap++) {
            const int s = tap / 3, dx = tap % 3 - 1;
            const int gy = y + s - 1;
            if (gy < 0 || gy > 255) continue;
            const uint32_t sah = sb + CV_AH(s);
            const uint32_t sal = sb + CV_AL(s);
            const int ar = px0 + (lane & 15) + 1 + dx;
            const unsigned wb0 = (unsigned)(((tap*NCB + cb)*2 + oh)*2)*128 + lane;
#pragma unroll
            for (int ks = 0; ks < 4; ks++) {
                uint32_t ah[2][4], al[2][4], bh[2][4], bl[2][4];
                *(uint4*)bh[0] = wfh[wb0        + ks*32];
                *(uint4*)bh[1] = wfh[wb0 + 128  + ks*32];
                *(uint4*)bl[0] = wfl[wb0        + ks*32];
                *(uint4*)bl[1] = wfl[wb0 + 128  + ks*32];
                const int acolb = ks*32 + (lane >> 4)*16;
                ldsm_x4(sah + SWZ128( ar      *128 + acolb), ah[0]);
                ldsm_x4(sah + SWZ128((ar + 16)*128 + acolb), ah[1]);
                ldsm_x4(sal + SWZ128( ar      *128 + acolb), al[0]);
                ldsm_x4(sal + SWZ128((ar + 16)*128 + acolb), al[1]);
#pragma unroll
                for (int term = 0; term < 3; term++)
#pragma unroll
                    for (int mi = 0; mi < 2; mi++)
#pragma unroll
                        for (int g = 0; g < 2; g++) {
                            const uint32_t* A = (term == 2) ? al[mi] : ah[mi];
                            const uint32_t* B = (term == 1) ? bl[g]  : bh[g];
                            mma_bf16(d[mi][g*2],     A, &B[0]);
                            mma_bf16(d[mi][g*2 + 1], A, &B[2]);
                        }
            }
        }
        __syncthreads();
    }

    const int rr  = lane >> 2;
    const int rc2 = (lane & 3) * 2;
#pragma unroll
    for (int mi = 0; mi < 2; mi++)
#pragma unroll
    for (int ni = 0; ni < 4; ni++) {
        int oc = oc0 + (ni >> 1)*16 + (ni & 1)*8 + rc2;
        float b0v = bias[oc], b1v = bias[oc + 1];
#pragma unroll
        for (int hh = 0; hh < 2; hh++) {
            int pxl = px0 + mi*16 + rr + hh*8;
            int x = x0 + pxl;
            float v0 = fmaxf(d[mi][ni][hh*2 + 0] + b0v, 0.f);
            float v1 = fmaxf(d[mi][ni][hh*2 + 1] + b1v, 0.f);
            if (MODE == 1) {
                size_t base = (((size_t)(b*RESOC + y)*RESOC) + x)*COUTC + oc;
                unsigned hi = bfpair(v0, v1);
                float l0 = v0 - bflo_f(hi), l1 = v1 - bfhi_f(hi);
                unsigned lo = bfpair(l0, l1);
                *(u32*)&g_x1h[base] = hi;
                *(u32*)&g_x1l[base] = lo;
            } else {
                size_t cm0 = (((size_t)(b*COUTC + oc)*RESOC) + y)*RESOC + x;
                size_t cm1 = cm0 + (size_t)RESOC*RESOC;
                float r0 = v0 + xout[cm0], r1 = v1 + xout[cm1];
                xout[cm0] = r0; xout[cm1] = r1;
                *(float2*)&g_xt[(((size_t)(b*RESOC + y)*RESOC) + x)*COUTC + oc] =
                    make_float2(r0, r1);
            }
        }
    }
}

// ---------------- fused point pipeline (persistent, B via fragment LDG) ---
#define PT_A1H 0
#define PT_A1L 8192
#define PT_HH  16384
#define PT_HL  49152
#define PT_IDX 81920
#define PT_SMEM (81920 + 512)
#define PT_TILES 6250

__global__ __launch_bounds__(256, 2) void points_kernel(
    const float* __restrict__ p,   const float* __restrict__ c_last,
    const float* __restrict__ bf1, const float* __restrict__ bf2,
    const float* __restrict__ bfc,
    float* __restrict__ fea, float* __restrict__ cout)
{
    extern __shared__ char smem[];
    const uint32_t sb = smem_u32(smem);
    int* idx_s = (int*)(smem + PT_IDX);

    const int t = threadIdx.x;
    const int lane = t & 31, wid = t >> 5;

    const uint4* __restrict__ w1fh = (const uint4*)g_pw1fh;
    const uint4* __restrict__ w1fl = (const uint4*)g_pw1fl;
    const uint4* __restrict__ w2fh = (const uint4*)g_pw2fh;
    const uint4* __restrict__ w2fl = (const uint4*)g_pw2fl;

    const int rr  = lane >> 2;
    const int rc2 = (lane & 3) * 2;

#pragma unroll 1
    for (int tile = blockIdx.x; tile < PT_TILES; tile += gridDim.x) {
        {
            int pt = t >> 2, part = t & 3;
            int g = tile*64 + pt;
            int b = g / NPTSC;
            float px = p[(size_t)g*3 + 0], py = p[(size_t)g*3 + 1];
            float ix = fminf(fmaxf(px*255.f, 0.f), 255.f);
            float iy = fminf(fmaxf(py*255.f, 0.f), 255.f);
            float x0f = floorf(ix), y0f = floorf(iy);
            int x0 = (int)x0f, y0i = (int)y0f;
            int x1 = min(x0 + 1, 255), y1 = min(y0i + 1, 255);
            float wx = ix - x0f, wy = iy - y0f;
            float w00 = (1.f-wx)*(1.f-wy), w01 = wx*(1.f-wy);
            float w10 = (1.f-wx)*wy,       w11 = wx*wy;
            const float* f00 = &g_xt[(((size_t)(b*RESOC + y0i)*RESOC) + x0)*COUTC + part*16];
            const float* f01 = &g_xt[(((size_t)(b*RESOC + y0i)*RESOC) + x1)*COUTC + part*16];
            const float* f10 = &g_xt[(((size_t)(b*RESOC + y1 )*RESOC) + x0)*COUTC + part*16];
            const float* f11 = &g_xt[(((size_t)(b*RESOC + y1 )*RESOC) + x1)*COUTC + part*16];
#pragma unroll
            for (int i = 0; i < 4; i++) {
                float4 a = *(const float4*)&f00[i*4];
                float4 bq = *(const float4*)&f01[i*4];
                float4 cq = *(const float4*)&f10[i*4];
                float4 dq = *(const float4*)&f11[i*4];
                float r0 = a.x*w00 + bq.x*w01 + cq.x*w10 + dq.x*w11;
                float r1 = a.y*w00 + bq.y*w01 + cq.y*w10 + dq.y*w11;
                float r2 = a.z*w00 + bq.z*w01 + cq.z*w10 + dq.z*w11;
                float r3 = a.w*w00 + bq.w*w01 + cq.w*w10 + dq.w*w11;
                unsigned h0 = bfpair(r0, r1), h1 = bfpair(r2, r3);
                float l0 = r0 - bflo_f(h0), l1 = r1 - bfhi_f(h0);
                float l2 = r2 - bflo_f(h1), l3 = r3 - bfhi_f(h1);
                unsigned q0 = bfpair(l0, l1), q1 = bfpair(l2, l3);
                unsigned sw = SWZ128((unsigned)(pt*128 + part*32 + (i >> 1)*16)) + (i & 1)*8;
                *(uint2*)(smem + PT_A1H + sw) = make_uint2(h0, h1);
                *(uint2*)(smem + PT_A1L + sw) = make_uint2(q0, q1);
            }
            if (part == 0) {
                int gx = min(max((int)(px*256.f), 0), 255);
                int gy = min(max((int)(py*256.f), 0), 255);
                int cell = gy*256 + gx;
                idx_s[pt] = cell;
                atomicAdd(&g_cnt[b*65536 + cell], 1u);
            }
            const float* cls = c_last + (size_t)g*128 + part*32;
            int kc = 2 + (part >> 1);
#pragma unroll
            for (int grp = 0; grp < 4; grp++) {
                float f[8];
                float4 u0 = ((const float4*)cls)[grp*2];
                float4 u1 = ((const float4*)cls)[grp*2 + 1];
                f[0]=u0.x; f[1]=u0.y; f[2]=u0.z; f[3]=u0.w;
                f[4]=u1.x; f[5]=u1.y; f[6]=u1.z; f[7]=u1.w;
                uint4 hv, lv; cvt_hilo8(f, hv, lv);
                int col = (part*32 + grp*8) & 63;
                unsigned sw = SWZ128((unsigned)(pt*128 + col*2));
                *(uint4*)(smem + PT_HH + kc*8192 + sw) = hv;
                *(uint4*)(smem + PT_HL + kc*8192 + sw) = lv;
            }
        }
        __syncthreads();

        {
            const int pt0 = (wid & 1) * 32;
            const int oh1 = wid >> 1;
            const int j0  = oh1 * 32;
            float d[2][4][4];
#pragma unroll
            for (int mi = 0; mi < 2; mi++)
#pragma unroll
                for (int ni = 0; ni < 4; ni++)
#pragma unroll
                    for (int r = 0; r < 4; r++) d[mi][ni][r] = 0.f;

            const unsigned wb0 = (unsigned)(oh1*2)*128 + lane;
#pragma unroll
            for (int ks = 0; ks < 4; ks++) {
                uint32_t ah[2][4], al[2][4], bh[2][4], bl[2][4];
                *(uint4*)bh[0] = w1fh[wb0       + ks*32];
                *(uint4*)bh[1] = w1fh[wb0 + 128 + ks*32];
                *(uint4*)bl[0] = w1fl[wb0       + ks*32];
                *(uint4*)bl[1] = w1fl[wb0 + 128 + ks*32];
                const int arow  = lane & 15;
                const int acolb = ks*32 + (lane >> 4)*16;
                ldsm_x4(sb + PT_A1H + SWZ128((pt0 +      arow)*128 + acolb), ah[0]);
                ldsm_x4(sb + PT_A1H + SWZ128((pt0 + 16 + arow)*128 + acolb), ah[1]);
                ldsm_x4(sb + PT_A1L + SWZ128((pt0 +      arow)*128 + acolb), al[0]);
                ldsm_x4(sb + PT_A1L + SWZ128((pt0 + 16 + arow)*128 + acolb), al[1]);
#pragma unroll
                for (int term = 0; term < 3; term++)
#pragma unroll
                    for (int mi = 0; mi < 2; mi++)
#pragma unroll
                        for (int g = 0; g < 2; g++) {
                            const uint32_t* A = (term == 2) ? al[mi] : ah[mi];
                            const uint32_t* B = (term == 1) ? bl[g]  : bh[g];
                            mma_bf16(d[mi][g*2],     A, &B[0]);
                            mma_bf16(d[mi][g*2 + 1], A, &B[2]);
                        }
            }
#pragma unroll
            for (int mi = 0; mi < 2; mi++)
#pragma unroll
            for (int ni = 0; ni < 4; ni++) {
                int j = j0 + (ni >> 1)*16 + (ni & 1)*8 + rc2;
                float b0v = bf1[j], b1v = bf1[j + 1];
                int kc = j >> 6, col = j & 63;
#pragma unroll
                for (int hh = 0; hh < 2; hh++) {
                    int pt = pt0 + mi*16 + rr + hh*8;
                    float v0 = fmaxf(d[mi][ni][hh*2 + 0] + b0v, 0.f);
                    float v1 = fmaxf(d[mi][ni][hh*2 + 1] + b1v, 0.f);
                    unsigned hi = bfpair(v0, v1);
                    float l0 = v0 - bflo_f(hi), l1 = v1 - bfhi_f(hi);
                    unsigned lo = bfpair(l0, l1);
                    unsigned sw = SWZ128((unsigned)(pt*128 + (col & ~7)*2)) + (col & 7)*2;
                    *(u32*)(smem + PT_HH + kc*8192 + sw) = hi;
                    *(u32*)(smem + PT_HL + kc*8192 + sw) = lo;
                }
            }
        }
        __syncthreads();

        {
            const int m0 = (wid & 3) * 16;
            const int oh2 = wid >> 2;
            const int o0 = oh2 * 32;
            float d[4][4];
#pragma unroll
            for (int ni = 0; ni < 4; ni++)
#pragma unroll
                for (int r = 0; r < 4; r++) d[ni][r] = 0.f;

#pragma unroll 1
            for (int ks = 0; ks < 16; ks++) {
                const int kc = ks >> 2, kk = ks & 3;
                uint32_t ah[4], al[4], bh[2][4], bl[2][4];
                const unsigned wb = (unsigned)(((kc*2 + oh2)*2)*4 + kk)*32 + lane;
                *(uint4*)bh[0] = w2fh[wb];
                *(uint4*)bh[1] = w2fh[wb + 128];
                *(uint4*)bl[0] = w2fl[wb];
                *(uint4*)bl[1] = w2fl[wb + 128];
                const int arow  = lane & 15;
                const int acolb = kk*32 + (lane >> 4)*16;
                ldsm_x4(sb + PT_HH + kc*8192 + SWZ128((m0 + arow)*128 + acolb), ah);
                ldsm_x4(sb + PT_HL + kc*8192 + SWZ128((m0 + arow)*128 + acolb), al);
#pragma unroll
                for (int term = 0; term < 3; term++)
#pragma unroll
                    for (int g = 0; g < 2; g++) {
                        const uint32_t* A = (term == 2) ? al : ah;
                        const uint32_t* B = (term == 1) ? bl[g] : bh[g];
                        mma_bf16(d[g*2],     A, &B[0]);
                        mma_bf16(d[g*2 + 1], A, &B[2]);
                    }
            }
#pragma unroll
            for (int ni = 0; ni < 4; ni++) {
                int o = o0 + (ni >> 1)*16 + (ni & 1)*8 + rc2;
                float b0v = bf2[o] + bfc[o], b1v = bf2[o + 1] + bfc[o + 1];
#pragma unroll
                for (int hh = 0; hh < 2; hh++) {
                    int pt = m0 + rr + hh*8;
                    int g = tile*64 + pt;
                    int b = g / NPTSC;
                    int cell = idx_s[pt];
                    float cv0 = d[ni][hh*2 + 0] + b0v;
                    float cv1 = d[ni][hh*2 + 1] + b1v;
                    *(float2*)&cout[(size_t)g*64 + o] = make_float2(cv0, cv1);
                    atomicAdd(&fea[((size_t)(b*COUTC + o    ))*65536 + cell], cv0);
                    atomicAdd(&fea[((size_t)(b*COUTC + o + 1))*65536 + cell], cv1);
                }
            }
        }
        __syncthreads();
    }
}

// ---------------- scatter-mean finalize -----------------------------------
__global__ __launch_bounds__(256) void finalize_kernel(float* __restrict__ fea) {
    size_t i = (size_t)blockIdx.x * 256 + threadIdx.x;
    size_t stride = (size_t)gridDim.x * 256;
    for (size_t e = i; e < (size_t)BB*COUTC*RESOC*RESOC; e += stride) {
        unsigned cell = (unsigned)(e & 65535u);
        unsigned b = (unsigned)(e >> 22);
        unsigned c = g_cnt[b*65536 + cell];
        fea[e] *= 1.f / (float)(c > 1u ? c : 1u);
    }
}

// ---------------- launch ---------------------------------------------------
extern "C" void kernel_launch(void* const* d_in, const int* in_sizes, int n_in,
                              void* d_out, int out_size) {
    (void)in_sizes; (void)n_in; (void)out_size;
    const float* p         = (const float*)d_in[0];
    const float* from_up   = (const float*)d_in[1];
    const float* from_down = (const float*)d_in[2];
    const float* x_after   = (const float*)d_in[3];
    const float* c_last    = (const float*)d_in[4];
    const float* W_up      = (const float*)d_in[5];
    const float* b_up      = (const float*)d_in[6];
    const float* W1        = (const float*)d_in[7];
    const float* b1        = (const float*)d_in[8];
    const float* W2        = (const float*)d_in[9];
    const float* b2        = (const float*)d_in[10];
    const float* Wc        = (const float*)d_in[11];
    const float* bc        = (const float*)d_in[12];
    const float* Wf1       = (const float*)d_in[13];
    const float* bf1       = (const float*)d_in[14];
    const float* Wf2       = (const float*)d_in[15];
    const float* bf2       = (const float*)d_in[16];
    const float* Wfc       = (const float*)d_in[17];
    const float* bfc       = (const float*)d_in[18];

    float* out  = (float*)d_out;
    float* fea  = out;                        // (B,64,256,256)
    float* xout = out + (size_t)16777216;     // (B,64,256,256)
    float* cout = out + (size_t)33554432;     // (B,NPTS,64)

    static cudaStream_t s1 = nullptr, s2 = nullptr, s3 = nullptr;
    static cudaEvent_t eStart = nullptr, eW = nullptr, eZero = nullptr,
                       eUpc1 = nullptr, eTr = nullptr;
    if (!s1) {
        cudaStreamCreateWithFlags(&s1, cudaStreamNonBlocking);
        cudaStreamCreateWithFlags(&s2, cudaStreamNonBlocking);
        cudaStreamCreateWithFlags(&s3, cudaStreamNonBlocking);
        cudaEventCreateWithFlags(&eStart, cudaEventDisableTiming);
        cudaEventCreateWithFlags(&eW,     cudaEventDisableTiming);
        cudaEventCreateWithFlags(&eZero,  cudaEventDisableTiming);
        cudaEventCreateWithFlags(&eUpc1,  cudaEventDisableTiming);
        cudaEventCreateWithFlags(&eTr,    cudaEventDisableTiming);
        cudaFuncSetAttribute(points_kernel, cudaFuncAttributeMaxDynamicSharedMemorySize, PT_SMEM);
        cudaFuncSetAttribute(upconv_mma_kernel<0>, cudaFuncAttributeMaxDynamicSharedMemorySize, UPC_SMEM);
        cudaFuncSetAttribute(upconv_mma_kernel<1>, cudaFuncAttributeMaxDynamicSharedMemorySize, UPC_SMEM);
        cudaFuncSetAttribute(conv_mma_kernel<1>, cudaFuncAttributeMaxDynamicSharedMemorySize, CV_SMEM);
        cudaFuncSetAttribute(conv_mma_kernel<2>, cudaFuncAttributeMaxDynamicSharedMemorySize, CV_SMEM);
    }

    // fork point on the (possibly capturing) origin stream
    cudaEventRecord(eStart, 0);

    // origin: weight convert, then upconv0 (conv1's critical path)
    wconv_kernel<<<784, 256>>>(W1, W2, Wf1, Wf2, Wfc, W_up, Wc);
    cudaEventRecord(eW, 0);
    upconv_mma_kernel<0><<<dim3(2, 128, 4), 256, UPC_SMEM>>>(from_up, b_up, nullptr);

    // s1: zero fea + counts (needed only by points)
    cudaStreamWaitEvent(s1, eStart, 0);
    zero_kernel<<<2048, 256, 0, s1>>>(fea);
    cudaEventRecord(eZero, s1);

    // s2: upconv1 -> xout residual (needed only by conv2 epilogue)
    cudaStreamWaitEvent(s2, eW, 0);
    upconv_mma_kernel<1><<<dim3(2, 128, 4), 256, UPC_SMEM, s2>>>(x_after, bc, xout);
    cudaEventRecord(eUpc1, s2);

    // s3: transpose from_down (needed by conv1)
    cudaStreamWaitEvent(s3, eStart, 0);
    transpose_kernel<<<dim3(8, 256, 4), 256, 0, s3>>>(from_down);
    cudaEventRecord(eTr, s3);

    // origin: conv1 after upconv0 (ordered) + transpose (event)
    cudaStreamWaitEvent(0, eTr, 0);
    conv_mma_kernel<1><<<dim3(2, 256, 4), 256, CV_SMEM>>>(b1, nullptr);

    // conv2 after conv1 (ordered) + upconv1 (event)
    cudaStreamWaitEvent(0, eUpc1, 0);
    conv_mma_kernel<2><<<dim3(2, 256, 4), 256, CV_SMEM>>>(b2, xout);

    // points after conv2 (ordered) + zero (event)
    cudaStreamWaitEvent(0, eZero, 0);
    points_kernel<<<296, 256, PT_SMEM>>>(p, c_last, bf1, bf2, bfc, fea, cout);
    finalize_kernel<<<8192, 256>>>(fea);
}